// round 9
// baseline (speedup 1.0000x reference)
#include <cuda_runtime.h>
#include <math.h>
#include <stdint.h>

// Problem constants
#define NB 100000
#define NC 10000
#define EB 400000
#define EC 80000
#define CAP 64

// ---------------------------------------------------------------------------
// Scratch layout (floats; int regions reinterpreted)
// ---------------------------------------------------------------------------
constexpr long long O_CXLR = 0;                                   // [NC,1024]
constexpr long long O_CH1  = O_CXLR + (long long)NC * 1024;       // [NC,512]
constexpr long long O_CXLR2= O_CH1  + (long long)NC * 512;        // [NC,256]
constexpr long long O_CH2  = O_CXLR2+ (long long)NC * 256;        // [NC,128]
constexpr long long O_FAW  = O_CH2  + (long long)NC * 128;        // [192,1024]
constexpr long long O_WM   = O_FAW  + (long long)192 * 1024;      // [NB,2]
constexpr long long O_WC1  = O_WM   + (long long)NB * 2;          // [32,1024]
constexpr long long O_WC2  = O_WC1  + (long long)32 * 1024;       // [512,256]
constexpr long long O_WB1  = O_WC2  + (long long)512 * 256;       // [192,1024]
constexpr long long O_WB2  = O_WB1  + (long long)192 * 1024;      // [512,256]
constexpr long long O_BXLR = O_WB2  + (long long)512 * 256;       // [NB,1024]
constexpr long long O_BH1  = O_BXLR + (long long)NB * 1024;       // [NB,512]
constexpr long long O_BH2  = O_BH1  + (long long)NB * 512;        // [NB,128]
constexpr long long O_XL3  = O_BH2  + (long long)NB * 128;        // [NB,2]
constexpr long long O_XR3  = O_XL3  + (long long)NB * 2;          // [NB,2]
constexpr long long O_BCNT = O_XR3  + (long long)NB * 2;          // int [NB]
constexpr long long O_BEL  = O_BCNT + (long long)NB;              // int [NB*CAP]
constexpr long long O_CCNT = O_BEL  + (long long)NB * CAP;        // int [NC]
constexpr long long O_CEL  = O_CCNT + (long long)NC;              // int [NC*CAP]
constexpr long long SCRATCH_TOTAL = O_CEL + (long long)NC * CAP;

__device__ float g_scratch[SCRATCH_TOTAL];

// ---------------------------------------------------------------------------
__global__ void fillk(float* __restrict__ x, float v, long long n) {
    long long i = (long long)blockIdx.x * blockDim.x + threadIdx.x;
    if (i < n) x[i] = v;
}

__global__ void izero(int* __restrict__ p, int n) {
    int i = blockIdx.x * blockDim.x + threadIdx.x;
    if (i < n) p[i] = 0;
}

// Bucket lists store SRC node ids directly.
__global__ void build_lists(const int* __restrict__ ei, int E,
                            int* __restrict__ cnt, int* __restrict__ el)
{
    int e = blockIdx.x * blockDim.x + threadIdx.x;
    if (e >= E) return;
    int s = ei[e];
    int d = ei[E + e];
    int slot = atomicAdd(&cnt[d], 1);
    if (slot < CAP) el[(long long)d * CAP + slot] = s;
}

// out[k][0..M-1] = a[k][...], out[k][M..2M-1] = b[k][...]
__global__ void concat2(const float* __restrict__ a, const float* __restrict__ b,
                        float* __restrict__ out, int K, int M)
{
    int i = blockIdx.x * blockDim.x + threadIdx.x;
    if (i >= K * 2 * M) return;
    int k = i / (2 * M), c = i % (2 * M);
    out[i] = (c < M) ? a[k * M + c] : b[k * M + (c - M)];
}

// fa_w1 (8,192,128) -> [192, 1024] with col = h*128 + j
__global__ void transpose_faw1(const float* __restrict__ w, float* __restrict__ out)
{
    int i = blockIdx.x * blockDim.x + threadIdx.x;
    if (i >= 8 * 192 * 128) return;
    int h = i / (192 * 128), r = (i / 128) % 192, j = i % 128;
    out[r * 1024 + h * 128 + j] = w[i];
}

// ---------------------------------------------------------------------------
// TF32 tensor-core GEMM, 3-stage cp.async pipeline, one barrier per k-tile.
// Fragments: A via ldmatrix.x4.b16 from [m][k] smem; B via float4 LDS with
// column-interleaved MMA mapping (MMA nj covers global cols {wn + 4*i + nj}).
// C[N,M] = A[N,K] @ B[K,M] (+bias, optional relu)
// 128x128x32 CTA tile, 8 warps, warp tile 64x32, mma.m16n8k8.tf32.
// MODE 0: plain A.  MODE 1: A = gather(bf|cx[map]), K=192.
// MODE 2: gather + per-row wmean scale (region k<64 vs k>=64).
// fa epilogue (w2 != null): per-head MLP head reduced in-register, softmax,
// atomicAdd 0.125*softmax into wmean. head = blockIdx.x.
// ---------------------------------------------------------------------------
#define AS_STRIDE 36
#define BS_STRIDE 132
#define ABUF (128 * AS_STRIDE)
#define BBUF (32 * BS_STRIDE)
#define BUFSZ (ABUF + BBUF)
#define STAGES 3
#define GEMM_SMEM_BYTES (STAGES * BUFSZ * 4)

__device__ __forceinline__ void cp16(uint32_t d, const void* s, bool pred) {
    int sz = pred ? 16 : 0;
    asm volatile("cp.async.ca.shared.global [%0], [%1], 16, %2;\n"
                 :: "r"(d), "l"(s), "r"(sz));
}

__device__ __forceinline__ void mma_tf32(float* c, unsigned a0, unsigned a1,
                                         unsigned a2, unsigned a3,
                                         unsigned b0, unsigned b1) {
    asm volatile(
        "mma.sync.aligned.m16n8k8.row.col.f32.tf32.tf32.f32 "
        "{%0,%1,%2,%3},{%4,%5,%6,%7},{%8,%9},{%0,%1,%2,%3};"
        : "+f"(c[0]), "+f"(c[1]), "+f"(c[2]), "+f"(c[3])
        : "r"(a0), "r"(a1), "r"(a2), "r"(a3), "r"(b0), "r"(b1));
}

__device__ __forceinline__ void ldsm4(unsigned& r0, unsigned& r1,
                                      unsigned& r2, unsigned& r3, uint32_t addr) {
    asm volatile("ldmatrix.sync.aligned.m8n8.x4.shared.b16 {%0,%1,%2,%3}, [%4];"
                 : "=r"(r0), "=r"(r1), "=r"(r2), "=r"(r3) : "r"(addr));
}

template<int MODE>
__global__ void __launch_bounds__(256, 2) tf32gemm(
    const float* __restrict__ A, const float* __restrict__ B,
    float* __restrict__ C, const float* __restrict__ bias,
    int N, int K, int M, int relu,
    const float* __restrict__ w2, const float* __restrict__ b2,
    float* __restrict__ wmean,
    const float* __restrict__ gsrc0,   // bf  [N,64]   (MODE>=1)
    const float* __restrict__ gsrc1,   // cx  [NC,128] (MODE>=1)
    const int*   __restrict__ gmap,    // map [N]      (MODE>=1)
    const float* __restrict__ ascale)  // wmean [N,2]  (MODE==2)
{
    extern __shared__ float sm[];
    int tid = threadIdx.x;
    int warp = tid >> 5, lane = tid & 31;
    int wm = (warp >> 2) * 64;
    int wn = (warp & 3) * 32;
    int g  = lane >> 2;
    int tg = lane & 3;
    int rowBase = blockIdx.y * 128;
    int colBase = blockIdx.x * 128;

    uint32_t sbase = (uint32_t)__cvta_generic_to_shared(sm);

    // ldmatrix per-lane source mapping (within current A buffer):
    // lanes 0-7  -> rows wm+mi*16+d,    cols ks..ks+3   (a0)
    // lanes 8-15 -> rows wm+mi*16+8+d,  cols ks..ks+3   (a1)
    // lanes16-23 -> rows wm+mi*16+d,    cols ks+4..ks+7 (a2)
    // lanes24-31 -> rows wm+mi*16+8+d,  cols ks+4..ks+7 (a3)
    int lgrp = lane >> 3, lrow = lane & 7;
    int a_m_off = (lgrp & 1) ? 8 : 0;
    int a_k_off = (lgrp & 2) ? 4 : 0;
    uint32_t a_lane_rel = (uint32_t)(((wm + lrow + a_m_off) * AS_STRIDE + a_k_off) * 4);

    float acc[4][4][4] = {};
    int T = K >> 5;

    // per-row wmean scales (MODE 2)
    float s0[8], s1[8];
    if (MODE == 2) {
        #pragma unroll
        for (int mi = 0; mi < 4; mi++) {
            #pragma unroll
            for (int hf = 0; hf < 2; hf++) {
                int gr = rowBase + wm + mi * 16 + g + hf * 8;
                int idx = mi * 2 + hf;
                if (gr < N) {
                    s0[idx] = ascale[(long long)gr * 2 + 0];
                    s1[idx] = ascale[(long long)gr * 2 + 1];
                } else { s0[idx] = 1.0f; s1[idx] = 1.0f; }
            }
        }
    }

    auto issue_tile = [&](int k0, int buf) {
        uint32_t abase = sbase + (uint32_t)(buf * BUFSZ) * 4u;
        uint32_t bbase = abase + (uint32_t)ABUF * 4u;
        #pragma unroll
        for (int it = 0; it < 4; it++) {
            int chunk = tid + it * 256;
            int r  = chunk >> 3;
            int kc = (chunk & 7) << 2;
            int gr = rowBase + r;
            bool pa = gr < N;
            const float* srcA;
            if (MODE == 0) {
                srcA = A + (long long)(pa ? gr : 0) * K + k0 + kc;
            } else {
                int k = k0 + kc;
                if (k < 64) {
                    srcA = gsrc0 + (long long)(pa ? gr : 0) * 64 + k;
                } else {
                    int m = pa ? gmap[gr] : 0;
                    srcA = gsrc1 + (long long)m * 128 + (k - 64);
                }
            }
            cp16(abase + (uint32_t)(r * AS_STRIDE + kc) * 4u, srcA, pa);
            int kk = chunk >> 5;
            int nn = (chunk & 31) << 2;
            const float* srcB = B + (long long)(k0 + kk) * M + colBase + nn;
            cp16(bbase + (uint32_t)(kk * BS_STRIDE + nn) * 4u, srcB, true);
        }
        asm volatile("cp.async.commit_group;\n");
    };

    issue_tile(0, 0);
    if (T > 1) issue_tile(32, 1);

    for (int t = 0; t < T; t++) {
        if (t + 1 < T) { asm volatile("cp.async.wait_group 1;\n"); }
        else           { asm volatile("cp.async.wait_group 0;\n"); }
        __syncthreads();
        if (t + 2 < T) issue_tile((t + 2) << 5, (t + 2) % STAGES);

        int stage = t % STAGES;
        const float* bs = sm + stage * BUFSZ + ABUF;
        uint32_t a_base = sbase + (uint32_t)(stage * BUFSZ) * 4u + a_lane_rel;
        bool reg1 = (MODE == 2) && ((t << 5) >= 64);

        #pragma unroll
        for (int ks = 0; ks < 32; ks += 8) {
            // B fragments: one float4 row-segment per k-row (covers nj=0..3)
            float4 blo = *(const float4*)&bs[(ks + tg) * BS_STRIDE + wn + 4 * g];
            float4 bhi = *(const float4*)&bs[(ks + tg + 4) * BS_STRIDE + wn + 4 * g];
            const float* blof = (const float*)&blo;
            const float* bhif = (const float*)&bhi;
            #pragma unroll
            for (int mi = 0; mi < 4; mi++) {
                unsigned a0, a1, a2, a3;
                ldsm4(a0, a1, a2, a3,
                      a_base + (uint32_t)((mi * 16 * AS_STRIDE + ks) * 4));
                if (MODE == 2) {
                    float sc0 = reg1 ? s1[mi * 2]     : s0[mi * 2];
                    float sc1 = reg1 ? s1[mi * 2 + 1] : s0[mi * 2 + 1];
                    a0 = __float_as_uint(__uint_as_float(a0) * sc0);
                    a1 = __float_as_uint(__uint_as_float(a1) * sc1);
                    a2 = __float_as_uint(__uint_as_float(a2) * sc0);
                    a3 = __float_as_uint(__uint_as_float(a3) * sc1);
                }
                #pragma unroll
                for (int nj = 0; nj < 4; nj++)
                    mma_tf32(acc[mi][nj], a0, a1, a2, a3,
                             __float_as_uint(blof[nj]), __float_as_uint(bhif[nj]));
            }
        }
    }

    // Column mapping: MMA nj, fragment col c (0..7) -> global col wn + 4*c + nj.
    // c0,c1 at cols 2tg, 2tg+1 -> wn+8tg+nj and wn+8tg+4+nj.
    if (w2 == nullptr) {
        #pragma unroll
        for (int mi = 0; mi < 4; mi++) {
            int row = rowBase + wm + mi * 16 + g;
            int col = colBase + wn + 8 * tg;
            float4 bb0 = make_float4(0.f, 0.f, 0.f, 0.f), bb1 = bb0;
            if (bias) {
                bb0 = *(const float4*)(bias + col);
                bb1 = *(const float4*)(bias + col + 4);
            }
            if (row < N) {
                float4 v0 = make_float4(acc[mi][0][0] + bb0.x, acc[mi][1][0] + bb0.y,
                                        acc[mi][2][0] + bb0.z, acc[mi][3][0] + bb0.w);
                float4 v1 = make_float4(acc[mi][0][1] + bb1.x, acc[mi][1][1] + bb1.y,
                                        acc[mi][2][1] + bb1.z, acc[mi][3][1] + bb1.w);
                if (relu) {
                    v0.x = fmaxf(v0.x, 0.f); v0.y = fmaxf(v0.y, 0.f);
                    v0.z = fmaxf(v0.z, 0.f); v0.w = fmaxf(v0.w, 0.f);
                    v1.x = fmaxf(v1.x, 0.f); v1.y = fmaxf(v1.y, 0.f);
                    v1.z = fmaxf(v1.z, 0.f); v1.w = fmaxf(v1.w, 0.f);
                }
                *(float4*)(C + (long long)row * M + col) = v0;
                *(float4*)(C + (long long)row * M + col + 4) = v1;
            }
            if (row + 8 < N) {
                float4 v2 = make_float4(acc[mi][0][2] + bb0.x, acc[mi][1][2] + bb0.y,
                                        acc[mi][2][2] + bb0.z, acc[mi][3][2] + bb0.w);
                float4 v3 = make_float4(acc[mi][0][3] + bb1.x, acc[mi][1][3] + bb1.y,
                                        acc[mi][2][3] + bb1.z, acc[mi][3][3] + bb1.w);
                if (relu) {
                    v2.x = fmaxf(v2.x, 0.f); v2.y = fmaxf(v2.y, 0.f);
                    v2.z = fmaxf(v2.z, 0.f); v2.w = fmaxf(v2.w, 0.f);
                    v3.x = fmaxf(v3.x, 0.f); v3.y = fmaxf(v3.y, 0.f);
                    v3.z = fmaxf(v3.z, 0.f); v3.w = fmaxf(v3.w, 0.f);
                }
                *(float4*)(C + (long long)(row + 8) * M + col) = v2;
                *(float4*)(C + (long long)(row + 8) * M + col + 4) = v3;
            }
        }
    } else {
        int h = blockIdx.x;
        float* srow = sm;
        __syncthreads();                    // all warps out of mainloop smem
        for (int i = tid; i < 256; i += 256) srow[i] = 0.0f;
        __syncthreads();

        #pragma unroll
        for (int mi = 0; mi < 4; mi++) {
            float p0a = 0.f, p1a = 0.f;
            float p0b = 0.f, p1b = 0.f;
            #pragma unroll
            for (int nj = 0; nj < 4; nj++) {
                int cr0 = wn + 8 * tg + nj;
                int cr1 = cr0 + 4;
                float bb0 = bias[colBase + cr0];
                float bb1 = bias[colBase + cr1];
                float2 wa = *(const float2*)(w2 + h * 256 + cr0 * 2);
                float2 wb = *(const float2*)(w2 + h * 256 + cr1 * 2);
                float v0 = fmaxf(acc[mi][nj][0] + bb0, 0.f);
                float v1 = fmaxf(acc[mi][nj][1] + bb1, 0.f);
                p0a += v0 * wa.x + v1 * wb.x;
                p1a += v0 * wa.y + v1 * wb.y;
                float u0 = fmaxf(acc[mi][nj][2] + bb0, 0.f);
                float u1 = fmaxf(acc[mi][nj][3] + bb1, 0.f);
                p0b += u0 * wa.x + u1 * wb.x;
                p1b += u0 * wa.y + u1 * wb.y;
            }
            int ra = wm + mi * 16 + g;
            atomicAdd(&srow[ra * 2 + 0], p0a);
            atomicAdd(&srow[ra * 2 + 1], p1a);
            atomicAdd(&srow[(ra + 8) * 2 + 0], p0b);
            atomicAdd(&srow[(ra + 8) * 2 + 1], p1b);
        }
        __syncthreads();
        if (tid < 128) {
            int grow = rowBase + tid;
            if (grow < N) {
                float sa = srow[tid * 2 + 0] + b2[h * 2 + 0];
                float sb = srow[tid * 2 + 1] + b2[h * 2 + 1];
                float mx = fmaxf(sa, sb);
                float e0 = expf(sa - mx), e1 = expf(sb - mx);
                float inv = 0.125f / (e0 + e1);
                atomicAdd(&wmean[(long long)grow * 2 + 0], e0 * inv);
                atomicAdd(&wmean[(long long)grow * 2 + 1], e1 * inv);
            }
        }
    }
}

// ---------------------------------------------------------------------------
// Fused GATv2 softmax+aggregate, online softmax, float4 per lane.
// One LPG-lane group per (dst, head); D == 4*LPG.
// ---------------------------------------------------------------------------
template<int LPG, int D, int H, bool RELU>
__global__ void gat_fused(const int* __restrict__ cnt, const int* __restrict__ el,
                          const float* __restrict__ xl, const float* __restrict__ xr,
                          int ldx,
                          const float* __restrict__ att, const float* __restrict__ bias,
                          float* __restrict__ out, int Nnodes)
{
    static_assert(D == 4 * LPG, "");
    long long t = (long long)blockIdx.x * blockDim.x + threadIdx.x;
    long long gidx = t / LPG;
    int lane = (int)(t % LPG);
    if (gidx >= (long long)Nnodes * H) return;
    int dst = (int)(gidx / H), h = (int)(gidx % H);

    float4 xr4 = *(const float4*)(xr + (long long)dst * ldx + h * D + lane * 4);
    float4 a4  = *(const float4*)(att + (long long)h * D + lane * 4);

    int c = cnt[dst]; if (c > CAP) c = CAP;
    const int* lst = el + (long long)dst * CAP;

    float mx = -1e30f, wsum = 0.0f;
    float4 acc = make_float4(0.f, 0.f, 0.f, 0.f);

    for (int i = 0; i <= c; i++) {
        int src = (i == c) ? dst : lst[i];
        float4 v = *(const float4*)(xl + (long long)src * ldx + h * D + lane * 4);
        float e0 = v.x + xr4.x; e0 = e0 > 0.f ? e0 : 0.2f * e0;
        float e1 = v.y + xr4.y; e1 = e1 > 0.f ? e1 : 0.2f * e1;
        float e2 = v.z + xr4.z; e2 = e2 > 0.f ? e2 : 0.2f * e2;
        float e3 = v.w + xr4.w; e3 = e3 > 0.f ? e3 : 0.2f * e3;
        float s = e0 * a4.x + e1 * a4.y + e2 * a4.z + e3 * a4.w;
        #pragma unroll
        for (int o = LPG / 2; o; o >>= 1) s += __shfl_xor_sync(0xffffffffu, s, o, LPG);
        if (s > mx) {
            float f = expf(mx - s);
            wsum *= f;
            acc.x *= f; acc.y *= f; acc.z *= f; acc.w *= f;
            mx = s;
        }
        float p = expf(s - mx);
        wsum += p;
        acc.x += p * v.x; acc.y += p * v.y; acc.z += p * v.z; acc.w += p * v.w;
    }

    float inv = 1.0f / wsum;
    const float* pb = bias + h * D + lane * 4;
    float4 o4;
    o4.x = acc.x * inv + pb[0];
    o4.y = acc.y * inv + pb[1];
    o4.z = acc.z * inv + pb[2];
    o4.w = acc.w * inv + pb[3];
    if (RELU) {
        o4.x = fmaxf(o4.x, 0.f); o4.y = fmaxf(o4.y, 0.f);
        o4.z = fmaxf(o4.z, 0.f); o4.w = fmaxf(o4.w, 0.f);
    }
    *(float4*)(out + ((long long)dst * H + h) * D + lane * 4) = o4;
}

// Layer 3 (H=1, D=2) fused with final log-softmax, writes d_out.
__global__ void gat3_lsm(const int* __restrict__ cnt, const int* __restrict__ el,
                         const float* __restrict__ xl, const float* __restrict__ xr,
                         const float* __restrict__ att, const float* __restrict__ bias,
                         float* __restrict__ out, int Nnodes)
{
    long long t = (long long)blockIdx.x * blockDim.x + threadIdx.x;
    long long gidx = t >> 1;
    int lane = (int)(t & 1);
    if (gidx >= Nnodes) return;
    int dst = (int)gidx;

    float xr_d = xr[(long long)dst * 2 + lane];
    float a_d  = att[lane];
    int c = cnt[dst]; if (c > CAP) c = CAP;
    const int* lst = el + (long long)dst * CAP;

    float mx = -1e30f, wsum = 0.0f, acc = 0.0f;
    for (int i = 0; i <= c; i++) {
        int src = (i == c) ? dst : lst[i];
        float xv = xl[(long long)src * 2 + lane];
        float v = xv + xr_d;
        v = v > 0.0f ? v : 0.2f * v;
        float s = v * a_d;
        s += __shfl_xor_sync(0xffffffffu, s, 1, 2);
        if (s > mx) {
            float f = expf(mx - s);
            wsum *= f; acc *= f; mx = s;
        }
        float p = expf(s - mx);
        wsum += p;
        acc += p * xv;
    }
    float v = acc / wsum + bias[lane];
    float o = __shfl_xor_sync(0xffffffffu, v, 1, 2);
    float m2 = fmaxf(v, o);
    float lse = m2 + logf(expf(v - m2) + expf(o - m2));
    out[(long long)dst * 2 + lane] = v - lse;
}

// ---------------------------------------------------------------------------
__global__ void small_xform(const float* __restrict__ x, const float* __restrict__ wl,
                            const float* __restrict__ wr, float* __restrict__ xl,
                            float* __restrict__ xr, int N, int K)
{
    int n = blockIdx.x * blockDim.x + threadIdx.x;
    if (n >= N) return;
    float a0 = 0, a1 = 0, b0 = 0, b1 = 0;
    const float* px = x + (long long)n * K;
    for (int k = 0; k < K; k++) {
        float v = px[k];
        a0 += v * wl[k * 2]; a1 += v * wl[k * 2 + 1];
        b0 += v * wr[k * 2]; b1 += v * wr[k * 2 + 1];
    }
    xl[n * 2] = a0; xl[n * 2 + 1] = a1;
    xr[n * 2] = b0; xr[n * 2 + 1] = b1;
}

// ---------------------------------------------------------------------------
static inline int cdivll(long long a, long long b) { return (int)((a + b - 1) / b); }

static void gemm0(const float* A, const float* B, float* C, const float* bias,
                  int N, int K, int M, int relu)
{
    dim3 grid(M / 128, (N + 127) / 128);
    tf32gemm<0><<<grid, 256, GEMM_SMEM_BYTES>>>(A, B, C, bias, N, K, M, relu,
        nullptr, nullptr, nullptr, nullptr, nullptr, nullptr, nullptr);
}

extern "C" void kernel_launch(void* const* d_in, const int* in_sizes, int n_in,
                              void* d_out, int out_size)
{
    int idx_bf = 0, idx_cf = 1, idx_bei, idx_cei, idx_map, base_w;
    if (in_sizes[2] == 2 * EB) { idx_bei = 2; idx_cei = 3; idx_map = 4; base_w = 5; }
    else                       { base_w = 2; idx_bei = 26; idx_cei = 27; idx_map = 28; }
    const float* bf  = (const float*)d_in[idx_bf];
    const float* cf  = (const float*)d_in[idx_cf];
    const int*   bei = (const int*)d_in[idx_bei];
    const int*   cei = (const int*)d_in[idx_cei];
    const int*   b2c = (const int*)d_in[idx_map];

    enum { C1WL, C1WR, C1ATT, C1B, C2WL, C2WR, C2ATT, C2B,
           FAW1, FAB1, FAW2, FAB2,
           B1WL, B1WR, B1ATT, B1B, B2WL, B2WR, B2ATT, B2B,
           B3WL, B3WR, B3ATT, B3B };
    const float* W[24];
    for (int i = 0; i < 24; i++) W[i] = (const float*)d_in[base_w + i];

    float* S;
    cudaGetSymbolAddress((void**)&S, g_scratch);
    cudaFuncSetAttribute(tf32gemm<0>, cudaFuncAttributeMaxDynamicSharedMemorySize, GEMM_SMEM_BYTES);
    cudaFuncSetAttribute(tf32gemm<1>, cudaFuncAttributeMaxDynamicSharedMemorySize, GEMM_SMEM_BYTES);
    cudaFuncSetAttribute(tf32gemm<2>, cudaFuncAttributeMaxDynamicSharedMemorySize, GEMM_SMEM_BYTES);

    float* c_xlr  = S + O_CXLR;
    float* c_h1   = S + O_CH1;
    float* c_xlr2 = S + O_CXLR2;
    float* c_h2   = S + O_CH2;
    float* faW    = S + O_FAW;
    float* wmean  = S + O_WM;
    float* Wc1    = S + O_WC1;
    float* Wc2    = S + O_WC2;
    float* Wb1    = S + O_WB1;
    float* Wb2    = S + O_WB2;
    float* b_xlr  = S + O_BXLR;
    float* b_h1   = S + O_BH1;
    float* b_h2   = S + O_BH2;
    float* xl3    = S + O_XL3;
    float* xr3    = S + O_XR3;
    int* bcnt = (int*)(S + O_BCNT);
    int* bel  = (int*)(S + O_BEL);
    int* ccnt = (int*)(S + O_CCNT);
    int* cel  = (int*)(S + O_CEL);

    // ---- Community prep + GNN ----
    concat2<<<cdivll(32 * 1024, 256), 256>>>(W[C1WL], W[C1WR], Wc1, 32, 512);
    izero<<<cdivll(NC, 256), 256>>>(ccnt, NC);
    build_lists<<<cdivll(EC, 256), 256>>>(cei, EC, ccnt, cel);
    gemm0(cf, Wc1, c_xlr, nullptr, NC, 32, 1024, 0);
    gat_fused<16, 64, 8, true><<<cdivll((long long)NC * 8 * 16, 256), 256>>>(
        ccnt, cel, c_xlr, c_xlr + 512, 1024, W[C1ATT], W[C1B], c_h1, NC);

    concat2<<<cdivll(512 * 256, 256), 256>>>(W[C2WL], W[C2WR], Wc2, 512, 128);
    gemm0(c_h1, Wc2, c_xlr2, nullptr, NC, 512, 256, 0);
    gat_fused<8, 32, 4, true><<<cdivll((long long)NC * 4 * 8, 256), 256>>>(
        ccnt, cel, c_xlr2, c_xlr2 + 128, 256, W[C2ATT], W[C2B], c_h2, NC);

    // ---- Feature-attention (A gathered in-GEMM; head fused in epilogue) ----
    transpose_faw1<<<cdivll(8 * 192 * 128, 256), 256>>>(W[FAW1], faW);
    fillk<<<cdivll((long long)NB * 2, 256), 256>>>(wmean, 0.0f, (long long)NB * 2);
    izero<<<cdivll(NB, 256), 256>>>(bcnt, NB);
    build_lists<<<cdivll(EB, 256), 256>>>(bei, EB, bcnt, bel);
    {
        dim3 grid(1024 / 128, (NB + 127) / 128);
        tf32gemm<1><<<grid, 256, GEMM_SMEM_BYTES>>>(
            nullptr, faW, nullptr, W[FAB1], NB, 192, 1024, 1,
            W[FAW2], W[FAB2], wmean, bf, c_h2, b2c, nullptr);
    }

    // ---- Building GNN (b1 A = gather * wmean, fused into GEMM) ----
    concat2<<<cdivll(192 * 1024, 256), 256>>>(W[B1WL], W[B1WR], Wb1, 192, 512);
    {
        dim3 grid(1024 / 128, (NB + 127) / 128);
        tf32gemm<2><<<grid, 256, GEMM_SMEM_BYTES>>>(
            nullptr, Wb1, b_xlr, nullptr, NB, 192, 1024, 0,
            nullptr, nullptr, nullptr, bf, c_h2, b2c, wmean);
    }
    gat_fused<16, 64, 8, true><<<cdivll((long long)NB * 8 * 16, 256), 256>>>(
        bcnt, bel, b_xlr, b_xlr + 512, 1024, W[B1ATT], W[B1B], b_h1, NB);

    concat2<<<cdivll(512 * 256, 256), 256>>>(W[B2WL], W[B2WR], Wb2, 512, 128);
    gemm0(b_h1, Wb2, b_xlr, nullptr, NB, 512, 256, 0);
    gat_fused<8, 32, 4, true><<<cdivll((long long)NB * 4 * 8, 256), 256>>>(
        bcnt, bel, b_xlr, b_xlr + 128, 256, W[B2ATT], W[B2B], b_h2, NB);

    small_xform<<<cdivll(NB, 256), 256>>>(b_h2, W[B3WL], W[B3WR], xl3, xr3, NB, 128);
    gat3_lsm<<<cdivll((long long)NB * 2, 256), 256>>>(
        bcnt, bel, xl3, xr3, W[B3ATT], W[B3B], (float*)d_out, NB);
}

// round 11
// speedup vs baseline: 1.1500x; 1.1500x over previous
#include <cuda_runtime.h>
#include <math.h>
#include <stdint.h>

// Problem constants
#define NB 100000
#define NC 10000
#define EB 400000
#define EC 80000
#define CAP 64

// ---------------------------------------------------------------------------
// Scratch layout (floats; int regions reinterpreted)
// ---------------------------------------------------------------------------
constexpr long long O_CXLR = 0;                                   // [NC,1024]
constexpr long long O_CH1  = O_CXLR + (long long)NC * 1024;       // [NC,512]
constexpr long long O_CXLR2= O_CH1  + (long long)NC * 512;        // [NC,256]
constexpr long long O_CH2  = O_CXLR2+ (long long)NC * 256;        // [NC,128]
constexpr long long O_FAW  = O_CH2  + (long long)NC * 128;        // [192,1024]
constexpr long long O_WM   = O_FAW  + (long long)192 * 1024;      // [NB,2]
constexpr long long O_WC1  = O_WM   + (long long)NB * 2;          // [32,1024]
constexpr long long O_WC2  = O_WC1  + (long long)32 * 1024;       // [512,256]
constexpr long long O_WB1  = O_WC2  + (long long)512 * 256;       // [192,1024]
constexpr long long O_WB2  = O_WB1  + (long long)192 * 1024;      // [512,256]
constexpr long long O_BXLR = O_WB2  + (long long)512 * 256;       // [NB,1024]
constexpr long long O_BH1  = O_BXLR + (long long)NB * 1024;       // [NB,512]
constexpr long long O_BH2  = O_BH1  + (long long)NB * 512;        // [NB,128]
constexpr long long O_XL3  = O_BH2  + (long long)NB * 128;        // [NB,2]
constexpr long long O_XR3  = O_XL3  + (long long)NB * 2;          // [NB,2]
constexpr long long O_ZFA  = O_XR3  + (long long)NB * 2;          // [NC,1024]
constexpr long long O_ZB1  = O_ZFA  + (long long)NC * 1024;       // [NC,1024]
constexpr long long O_BCNT = O_ZB1  + (long long)NC * 1024;       // int [NB]
constexpr long long O_BEL  = O_BCNT + (long long)NB;              // int [NB*CAP]
constexpr long long O_CCNT = O_BEL  + (long long)NB * CAP;        // int [NC]
constexpr long long O_CEL  = O_CCNT + (long long)NC;              // int [NC*CAP]
constexpr long long SCRATCH_TOTAL = O_CEL + (long long)NC * CAP;

__device__ float g_scratch[SCRATCH_TOTAL];

// ---------------------------------------------------------------------------
__global__ void fillk(float* __restrict__ x, float v, long long n) {
    long long i = (long long)blockIdx.x * blockDim.x + threadIdx.x;
    if (i < n) x[i] = v;
}

__global__ void izero(int* __restrict__ p, int n) {
    int i = blockIdx.x * blockDim.x + threadIdx.x;
    if (i < n) p[i] = 0;
}

// Bucket lists store SRC node ids directly.
__global__ void build_lists(const int* __restrict__ ei, int E,
                            int* __restrict__ cnt, int* __restrict__ el)
{
    int e = blockIdx.x * blockDim.x + threadIdx.x;
    if (e >= E) return;
    int s = ei[e];
    int d = ei[E + e];
    int slot = atomicAdd(&cnt[d], 1);
    if (slot < CAP) el[(long long)d * CAP + slot] = s;
}

// out[k][0..M-1] = a[k][...], out[k][M..2M-1] = b[k][...]
__global__ void concat2(const float* __restrict__ a, const float* __restrict__ b,
                        float* __restrict__ out, int K, int M)
{
    int i = blockIdx.x * blockDim.x + threadIdx.x;
    if (i >= K * 2 * M) return;
    int k = i / (2 * M), c = i % (2 * M);
    out[i] = (c < M) ? a[k * M + c] : b[k * M + (c - M)];
}

// fa_w1 (8,192,128) -> [192, 1024] with col = h*128 + j
__global__ void transpose_faw1(const float* __restrict__ w, float* __restrict__ out)
{
    int i = blockIdx.x * blockDim.x + threadIdx.x;
    if (i >= 8 * 192 * 128) return;
    int h = i / (192 * 128), r = (i / 128) % 192, j = i % 128;
    out[r * 1024 + h * 128 + j] = w[i];
}

// ---------------------------------------------------------------------------
// TF32 tensor-core GEMM, 3-stage cp.async pipeline, one barrier per k-tile.
// C[N,M] = A[N,K] @ B[K,M] (+bias, optional relu)
// 128x128x32 CTA tile, 8 warps, warp tile 64x32, mma.m16n8k8.tf32.
// MODE 0: plain store epilogue.
// MODE 1 (fa): epilogue = per-head MLP head with Z add:
//   v = relu(acc + Z[map[row]][col] + bias[col]); head-reduce vs w2;
//   softmax(+b2); atomicAdd 0.125*softmax into wmean. head = blockIdx.x.
// MODE 2 (b1): A fragments scaled by ascale[row*2+0];
//   store epilogue: C = acc + ascale[row*2+1] * Z[map[row]][col].
// ---------------------------------------------------------------------------
#define AS_STRIDE 36
#define BS_STRIDE 132
#define ABUF (128 * AS_STRIDE)
#define BBUF (32 * BS_STRIDE)
#define BUFSZ (ABUF + BBUF)
#define STAGES 3
#define GEMM_SMEM_BYTES (STAGES * BUFSZ * 4)

__device__ __forceinline__ void cp16(uint32_t d, const void* s, bool pred) {
    int sz = pred ? 16 : 0;
    asm volatile("cp.async.ca.shared.global [%0], [%1], 16, %2;\n"
                 :: "r"(d), "l"(s), "r"(sz));
}

__device__ __forceinline__ void mma_tf32(float* c, unsigned a0, unsigned a1,
                                         unsigned a2, unsigned a3,
                                         unsigned b0, unsigned b1) {
    asm volatile(
        "mma.sync.aligned.m16n8k8.row.col.f32.tf32.tf32.f32 "
        "{%0,%1,%2,%3},{%4,%5,%6,%7},{%8,%9},{%0,%1,%2,%3};"
        : "+f"(c[0]), "+f"(c[1]), "+f"(c[2]), "+f"(c[3])
        : "r"(a0), "r"(a1), "r"(a2), "r"(a3), "r"(b0), "r"(b1));
}

template<int MODE>
__global__ void __launch_bounds__(256, 2) tf32gemm(
    const float* __restrict__ A, const float* __restrict__ B,
    float* __restrict__ C, const float* __restrict__ bias,
    int N, int K, int M, int relu,
    const float* __restrict__ w2, const float* __restrict__ b2,
    float* __restrict__ wmean,
    const float* __restrict__ zsrc,    // [NC, M] (MODE 1/2)
    const int*   __restrict__ gmap,    // [N]     (MODE 1/2)
    const float* __restrict__ ascale)  // [N,2]   (MODE 2)
{
    extern __shared__ float sm[];
    int tid = threadIdx.x;
    int warp = tid >> 5, lane = tid & 31;
    int wm = (warp >> 2) * 64;
    int wn = (warp & 3) * 32;
    int g  = lane >> 2;
    int tg = lane & 3;
    int rowBase = blockIdx.y * 128;
    int colBase = blockIdx.x * 128;

    uint32_t sbase = (uint32_t)__cvta_generic_to_shared(sm);

    float acc[4][4][4] = {};
    int T = K >> 5;

    // per-row A scales (MODE 2)
    float s0[8];
    if (MODE == 2) {
        #pragma unroll
        for (int mi = 0; mi < 4; mi++) {
            #pragma unroll
            for (int hf = 0; hf < 2; hf++) {
                int gr = rowBase + wm + mi * 16 + g + hf * 8;
                s0[mi * 2 + hf] = (gr < N) ? ascale[(long long)gr * 2 + 0] : 1.0f;
            }
        }
    }

    auto issue_tile = [&](int k0, int buf) {
        uint32_t abase = sbase + (uint32_t)(buf * BUFSZ) * 4u;
        uint32_t bbase = abase + (uint32_t)ABUF * 4u;
        #pragma unroll
        for (int it = 0; it < 4; it++) {
            int chunk = tid + it * 256;
            int r  = chunk >> 3;
            int kc = (chunk & 7) << 2;
            int gr = rowBase + r;
            bool pa = gr < N;
            const float* srcA = A + (long long)(pa ? gr : 0) * K + k0 + kc;
            cp16(abase + (uint32_t)(r * AS_STRIDE + kc) * 4u, srcA, pa);
            int kk = chunk >> 5;
            int nn = (chunk & 31) << 2;
            const float* srcB = B + (long long)(k0 + kk) * M + colBase + nn;
            cp16(bbase + (uint32_t)(kk * BS_STRIDE + nn) * 4u, srcB, true);
        }
        asm volatile("cp.async.commit_group;\n");
    };

    issue_tile(0, 0);
    if (T > 1) issue_tile(32, 1);

    for (int t = 0; t < T; t++) {
        if (t + 1 < T) { asm volatile("cp.async.wait_group 1;\n"); }
        else           { asm volatile("cp.async.wait_group 0;\n"); }
        __syncthreads();
        if (t + 2 < T) issue_tile((t + 2) << 5, (t + 2) % STAGES);

        const float* as = sm + (t % STAGES) * BUFSZ;
        const float* bs = as + ABUF;

        #pragma unroll
        for (int ks = 0; ks < 32; ks += 8) {
            unsigned af[4][4], bf[4][2];
            #pragma unroll
            for (int mi = 0; mi < 4; mi++) {
                int m = wm + mi * 16 + g;
                float v0 = as[m * AS_STRIDE + ks + tg];
                float v1 = as[(m + 8) * AS_STRIDE + ks + tg];
                float v2 = as[m * AS_STRIDE + ks + tg + 4];
                float v3 = as[(m + 8) * AS_STRIDE + ks + tg + 4];
                if (MODE == 2) {
                    float sc0 = s0[mi * 2];
                    float sc1 = s0[mi * 2 + 1];
                    v0 *= sc0; v1 *= sc1; v2 *= sc0; v3 *= sc1;
                }
                af[mi][0] = __float_as_uint(v0);
                af[mi][1] = __float_as_uint(v1);
                af[mi][2] = __float_as_uint(v2);
                af[mi][3] = __float_as_uint(v3);
            }
            #pragma unroll
            for (int nj = 0; nj < 4; nj++) {
                int n = wn + nj * 8 + g;
                bf[nj][0] = __float_as_uint(bs[(ks + tg) * BS_STRIDE + n]);
                bf[nj][1] = __float_as_uint(bs[(ks + tg + 4) * BS_STRIDE + n]);
            }
            #pragma unroll
            for (int mi = 0; mi < 4; mi++)
                #pragma unroll
                for (int nj = 0; nj < 4; nj++)
                    mma_tf32(acc[mi][nj], af[mi][0], af[mi][1], af[mi][2], af[mi][3],
                             bf[nj][0], bf[nj][1]);
        }
    }

    if (MODE != 1) {
        // Store epilogue (MODE 0: plain; MODE 2: + ascale1 * Z[map[row]])
        #pragma unroll
        for (int mi = 0; mi < 4; mi++) {
            int row = rowBase + wm + mi * 16 + g;
            const float* z0p = nullptr; const float* z1p = nullptr;
            float w1a = 0.f, w1b = 0.f;
            if (MODE == 2) {
                if (row < N)     { z0p = zsrc + (long long)gmap[row] * M;
                                   w1a = ascale[(long long)row * 2 + 1]; }
                if (row + 8 < N) { z1p = zsrc + (long long)gmap[row + 8] * M;
                                   w1b = ascale[(long long)(row + 8) * 2 + 1]; }
            }
            #pragma unroll
            for (int nj = 0; nj < 4; nj++) {
                int col = colBase + wn + nj * 8 + tg * 2;
                float b0 = 0.f, b1 = 0.f;
                if (bias) { b0 = bias[col]; b1 = bias[col + 1]; }
                if (row < N) {
                    float2 v = make_float2(acc[mi][nj][0] + b0, acc[mi][nj][1] + b1);
                    if (MODE == 2) {
                        float2 zv = *(const float2*)(z0p + col);
                        v.x += w1a * zv.x; v.y += w1a * zv.y;
                    }
                    if (relu) { v.x = fmaxf(v.x, 0.f); v.y = fmaxf(v.y, 0.f); }
                    *(float2*)(C + (long long)row * M + col) = v;
                }
                if (row + 8 < N) {
                    float2 v = make_float2(acc[mi][nj][2] + b0, acc[mi][nj][3] + b1);
                    if (MODE == 2) {
                        float2 zv = *(const float2*)(z1p + col);
                        v.x += w1b * zv.x; v.y += w1b * zv.y;
                    }
                    if (relu) { v.x = fmaxf(v.x, 0.f); v.y = fmaxf(v.y, 0.f); }
                    *(float2*)(C + (long long)(row + 8) * M + col) = v;
                }
            }
        }
    } else {
        // fa-head epilogue with Z add. head = blockIdx.x.
        int h = blockIdx.x;
        float* srow = sm;
        __syncthreads();
        for (int i = tid; i < 256; i += 256) srow[i] = 0.0f;
        __syncthreads();

        #pragma unroll
        for (int mi = 0; mi < 4; mi++) {
            #pragma unroll
            for (int hf = 0; hf < 2; hf++) {
                int rrel = wm + mi * 16 + g + 8 * hf;
                int row = rowBase + rrel;
                if (row >= N) continue;
                const float* zrow = zsrc + (long long)gmap[row] * M + colBase;
                float p0 = 0.f, p1 = 0.f;
                #pragma unroll
                for (int nj = 0; nj < 4; nj++) {
                    int cr = wn + nj * 8 + tg * 2;
                    float a0 = acc[mi][nj][2 * hf];
                    float a1 = acc[mi][nj][2 * hf + 1];
                    float v0 = fmaxf(a0 + zrow[cr] + bias[colBase + cr], 0.f);
                    float v1 = fmaxf(a1 + zrow[cr + 1] + bias[colBase + cr + 1], 0.f);
                    float2 wa = *(const float2*)(w2 + h * 256 + cr * 2);
                    float2 wb = *(const float2*)(w2 + h * 256 + (cr + 1) * 2);
                    p0 += v0 * wa.x + v1 * wb.x;
                    p1 += v0 * wa.y + v1 * wb.y;
                }
                atomicAdd(&srow[rrel * 2 + 0], p0);
                atomicAdd(&srow[rrel * 2 + 1], p1);
            }
        }
        __syncthreads();
        if (tid < 128) {
            int grow = rowBase + tid;
            if (grow < N) {
                float sa = srow[tid * 2 + 0] + b2[h * 2 + 0];
                float sb = srow[tid * 2 + 1] + b2[h * 2 + 1];
                float mx = fmaxf(sa, sb);
                float e0 = expf(sa - mx), e1 = expf(sb - mx);
                float inv = 0.125f / (e0 + e1);
                atomicAdd(&wmean[(long long)grow * 2 + 0], e0 * inv);
                atomicAdd(&wmean[(long long)grow * 2 + 1], e1 * inv);
            }
        }
    }
}

// ---------------------------------------------------------------------------
// Fused GATv2 softmax+aggregate, online softmax, float4 per lane.
// One LPG-lane group per (dst, head); D == 4*LPG.
// ---------------------------------------------------------------------------
template<int LPG, int D, int H, bool RELU>
__global__ void gat_fused(const int* __restrict__ cnt, const int* __restrict__ el,
                          const float* __restrict__ xl, const float* __restrict__ xr,
                          int ldx,
                          const float* __restrict__ att, const float* __restrict__ bias,
                          float* __restrict__ out, int Nnodes)
{
    static_assert(D == 4 * LPG, "");
    long long t = (long long)blockIdx.x * blockDim.x + threadIdx.x;
    long long gidx = t / LPG;
    int lane = (int)(t % LPG);
    if (gidx >= (long long)Nnodes * H) return;
    int dst = (int)(gidx / H), h = (int)(gidx % H);

    float4 xr4 = *(const float4*)(xr + (long long)dst * ldx + h * D + lane * 4);
    float4 a4  = *(const float4*)(att + (long long)h * D + lane * 4);

    int c = cnt[dst]; if (c > CAP) c = CAP;
    const int* lst = el + (long long)dst * CAP;

    float mx = -1e30f, wsum = 0.0f;
    float4 acc = make_float4(0.f, 0.f, 0.f, 0.f);

    for (int i = 0; i <= c; i++) {
        int src = (i == c) ? dst : lst[i];
        float4 v = *(const float4*)(xl + (long long)src * ldx + h * D + lane * 4);
        float e0 = v.x + xr4.x; e0 = e0 > 0.f ? e0 : 0.2f * e0;
        float e1 = v.y + xr4.y; e1 = e1 > 0.f ? e1 : 0.2f * e1;
        float e2 = v.z + xr4.z; e2 = e2 > 0.f ? e2 : 0.2f * e2;
        float e3 = v.w + xr4.w; e3 = e3 > 0.f ? e3 : 0.2f * e3;
        float s = e0 * a4.x + e1 * a4.y + e2 * a4.z + e3 * a4.w;
        #pragma unroll
        for (int o = LPG / 2; o; o >>= 1) s += __shfl_xor_sync(0xffffffffu, s, o, LPG);
        if (s > mx) {
            float f = expf(mx - s);
            wsum *= f;
            acc.x *= f; acc.y *= f; acc.z *= f; acc.w *= f;
            mx = s;
        }
        float p = expf(s - mx);
        wsum += p;
        acc.x += p * v.x; acc.y += p * v.y; acc.z += p * v.z; acc.w += p * v.w;
    }

    float inv = 1.0f / wsum;
    const float* pb = bias + h * D + lane * 4;
    float4 o4;
    o4.x = acc.x * inv + pb[0];
    o4.y = acc.y * inv + pb[1];
    o4.z = acc.z * inv + pb[2];
    o4.w = acc.w * inv + pb[3];
    if (RELU) {
        o4.x = fmaxf(o4.x, 0.f); o4.y = fmaxf(o4.y, 0.f);
        o4.z = fmaxf(o4.z, 0.f); o4.w = fmaxf(o4.w, 0.f);
    }
    *(float4*)(out + ((long long)dst * H + h) * D + lane * 4) = o4;
}

// Layer 3 (H=1, D=2) fused with final log-softmax, writes d_out.
__global__ void gat3_lsm(const int* __restrict__ cnt, const int* __restrict__ el,
                         const float* __restrict__ xl, const float* __restrict__ xr,
                         const float* __restrict__ att, const float* __restrict__ bias,
                         float* __restrict__ out, int Nnodes)
{
    long long t = (long long)blockIdx.x * blockDim.x + threadIdx.x;
    long long gidx = t >> 1;
    int lane = (int)(t & 1);
    if (gidx >= Nnodes) return;
    int dst = (int)gidx;

    float xr_d = xr[(long long)dst * 2 + lane];
    float a_d  = att[lane];
    int c = cnt[dst]; if (c > CAP) c = CAP;
    const int* lst = el + (long long)dst * CAP;

    float mx = -1e30f, wsum = 0.0f, acc = 0.0f;
    for (int i = 0; i <= c; i++) {
        int src = (i == c) ? dst : lst[i];
        float xv = xl[(long long)src * 2 + lane];
        float v = xv + xr_d;
        v = v > 0.0f ? v : 0.2f * v;
        float s = v * a_d;
        s += __shfl_xor_sync(0xffffffffu, s, 1, 2);
        if (s > mx) {
            float f = expf(mx - s);
            wsum *= f; acc *= f; mx = s;
        }
        float p = expf(s - mx);
        wsum += p;
        acc += p * xv;
    }
    float v = acc / wsum + bias[lane];
    float o = __shfl_xor_sync(0xffffffffu, v, 1, 2);
    float m2 = fmaxf(v, o);
    float lse = m2 + logf(expf(v - m2) + expf(o - m2));
    out[(long long)dst * 2 + lane] = v - lse;
}

// ---------------------------------------------------------------------------
__global__ void small_xform(const float* __restrict__ x, const float* __restrict__ wl,
                            const float* __restrict__ wr, float* __restrict__ xl,
                            float* __restrict__ xr, int N, int K)
{
    int n = blockIdx.x * blockDim.x + threadIdx.x;
    if (n >= N) return;
    float a0 = 0, a1 = 0, b0 = 0, b1 = 0;
    const float* px = x + (long long)n * K;
    for (int k = 0; k < K; k++) {
        float v = px[k];
        a0 += v * wl[k * 2]; a1 += v * wl[k * 2 + 1];
        b0 += v * wr[k * 2]; b1 += v * wr[k * 2 + 1];
    }
    xl[n * 2] = a0; xl[n * 2 + 1] = a1;
    xr[n * 2] = b0; xr[n * 2 + 1] = b1;
}

// ---------------------------------------------------------------------------
static inline int cdivll(long long a, long long b) { return (int)((a + b - 1) / b); }

static void gemm0(const float* A, const float* B, float* C, const float* bias,
                  int N, int K, int M, int relu)
{
    dim3 grid(M / 128, (N + 127) / 128);
    tf32gemm<0><<<grid, 256, GEMM_SMEM_BYTES>>>(A, B, C, bias, N, K, M, relu,
        nullptr, nullptr, nullptr, nullptr, nullptr, nullptr);
}

extern "C" void kernel_launch(void* const* d_in, const int* in_sizes, int n_in,
                              void* d_out, int out_size)
{
    int idx_bf = 0, idx_cf = 1, idx_bei, idx_cei, idx_map, base_w;
    if (in_sizes[2] == 2 * EB) { idx_bei = 2; idx_cei = 3; idx_map = 4; base_w = 5; }
    else                       { base_w = 2; idx_bei = 26; idx_cei = 27; idx_map = 28; }
    const float* bf  = (const float*)d_in[idx_bf];
    const float* cf  = (const float*)d_in[idx_cf];
    const int*   bei = (const int*)d_in[idx_bei];
    const int*   cei = (const int*)d_in[idx_cei];
    const int*   b2c = (const int*)d_in[idx_map];

    enum { C1WL, C1WR, C1ATT, C1B, C2WL, C2WR, C2ATT, C2B,
           FAW1, FAB1, FAW2, FAB2,
           B1WL, B1WR, B1ATT, B1B, B2WL, B2WR, B2ATT, B2B,
           B3WL, B3WR, B3ATT, B3B };
    const float* W[24];
    for (int i = 0; i < 24; i++) W[i] = (const float*)d_in[base_w + i];

    float* S;
    cudaGetSymbolAddress((void**)&S, g_scratch);
    cudaFuncSetAttribute(tf32gemm<0>, cudaFuncAttributeMaxDynamicSharedMemorySize, GEMM_SMEM_BYTES);
    cudaFuncSetAttribute(tf32gemm<1>, cudaFuncAttributeMaxDynamicSharedMemorySize, GEMM_SMEM_BYTES);
    cudaFuncSetAttribute(tf32gemm<2>, cudaFuncAttributeMaxDynamicSharedMemorySize, GEMM_SMEM_BYTES);

    float* c_xlr  = S + O_CXLR;
    float* c_h1   = S + O_CH1;
    float* c_xlr2 = S + O_CXLR2;
    float* c_h2   = S + O_CH2;
    float* faW    = S + O_FAW;
    float* wmean  = S + O_WM;
    float* Wc1    = S + O_WC1;
    float* Wc2    = S + O_WC2;
    float* Wb1    = S + O_WB1;
    float* Wb2    = S + O_WB2;
    float* b_xlr  = S + O_BXLR;
    float* b_h1   = S + O_BH1;
    float* b_h2   = S + O_BH2;
    float* xl3    = S + O_XL3;
    float* xr3    = S + O_XR3;
    float* Zfa    = S + O_ZFA;
    float* Zb1    = S + O_ZB1;
    int* bcnt = (int*)(S + O_BCNT);
    int* bel  = (int*)(S + O_BEL);
    int* ccnt = (int*)(S + O_CCNT);
    int* cel  = (int*)(S + O_CEL);

    // ---- Community prep + GNN ----
    concat2<<<cdivll(32 * 1024, 256), 256>>>(W[C1WL], W[C1WR], Wc1, 32, 512);
    izero<<<cdivll(NC, 256), 256>>>(ccnt, NC);
    build_lists<<<cdivll(EC, 256), 256>>>(cei, EC, ccnt, cel);
    gemm0(cf, Wc1, c_xlr, nullptr, NC, 32, 1024, 0);
    gat_fused<16, 64, 8, true><<<cdivll((long long)NC * 8 * 16, 256), 256>>>(
        ccnt, cel, c_xlr, c_xlr + 512, 1024, W[C1ATT], W[C1B], c_h1, NC);

    concat2<<<cdivll(512 * 256, 256), 256>>>(W[C2WL], W[C2WR], Wc2, 512, 128);
    gemm0(c_h1, Wc2, c_xlr2, nullptr, NC, 512, 256, 0);
    gat_fused<8, 32, 4, true><<<cdivll((long long)NC * 4 * 8, 256), 256>>>(
        ccnt, cel, c_xlr2, c_xlr2 + 128, 256, W[C2ATT], W[C2B], c_h2, NC);

    // ---- Prep for building side ----
    transpose_faw1<<<cdivll(8 * 192 * 128, 256), 256>>>(W[FAW1], faW);
    concat2<<<cdivll(192 * 1024, 256), 256>>>(W[B1WL], W[B1WR], Wb1, 192, 512);
    fillk<<<cdivll((long long)NB * 2, 256), 256>>>(wmean, 0.0f, (long long)NB * 2);
    izero<<<cdivll(NB, 256), 256>>>(bcnt, NB);
    build_lists<<<cdivll(EB, 256), 256>>>(bei, EB, bcnt, bel);

    // ---- Low-rank precompute: Z = c_h2 @ W_hi (community rows only) ----
    gemm0(c_h2, faW + 64 * 1024, Zfa, nullptr, NC, 128, 1024, 0);
    gemm0(c_h2, Wb1 + 64 * 1024, Zb1, nullptr, NC, 128, 1024, 0);

    // ---- Feature attention: fah = bf @ faW_lo + Zfa[map]; head fused ----
    {
        dim3 grid(1024 / 128, (NB + 127) / 128);
        tf32gemm<1><<<grid, 256, GEMM_SMEM_BYTES>>>(
            bf, faW, nullptr, W[FAB1], NB, 64, 1024, 1,
            W[FAW2], W[FAB2], wmean, Zfa, b2c, nullptr);
    }

    // ---- Building GNN: b_xlr = (bf*wm0) @ Wb1_lo + wm1*Zb1[map] ----
    {
        dim3 grid(1024 / 128, (NB + 127) / 128);
        tf32gemm<2><<<grid, 256, GEMM_SMEM_BYTES>>>(
            bf, Wb1, b_xlr, nullptr, NB, 64, 1024, 0,
            nullptr, nullptr, nullptr, Zb1, b2c, wmean);
    }
    gat_fused<16, 64, 8, true><<<cdivll((long long)NB * 8 * 16, 256), 256>>>(
        bcnt, bel, b_xlr, b_xlr + 512, 1024, W[B1ATT], W[B1B], b_h1, NB);

    concat2<<<cdivll(512 * 256, 256), 256>>>(W[B2WL], W[B2WR], Wb2, 512, 128);
    gemm0(b_h1, Wb2, b_xlr, nullptr, NB, 512, 256, 0);
    gat_fused<8, 32, 4, true><<<cdivll((long long)NB * 4 * 8, 256), 256>>>(
        bcnt, bel, b_xlr, b_xlr + 128, 256, W[B2ATT], W[B2B], b_h2, NB);

    small_xform<<<cdivll(NB, 256), 256>>>(b_h2, W[B3WL], W[B3WR], xl3, xr3, NB, 128);
    gat3_lsm<<<cdivll((long long)NB * 2, 256), 256>>>(
        bcnt, bel, xl3, xr3, W[B3ATT], W[B3B], (float*)d_out, NB);
}

// round 12
// speedup vs baseline: 1.3868x; 1.2058x over previous
#include <cuda_runtime.h>
#include <cuda_fp16.h>
#include <math.h>
#include <stdint.h>

// Problem constants
#define NB 100000
#define NC 10000
#define EB 400000
#define EC 80000
#define CAP 64

// halfs -> float slots
#define HF(n) (((n) + 1) / 2)

// ---------------------------------------------------------------------------
// Scratch layout (float units; half/int regions reinterpreted)
// ---------------------------------------------------------------------------
constexpr long long O_CFH   = 0;                                    // h [NC,32]
constexpr long long O_CXLR  = O_CFH   + HF((long long)NC * 32);     // h [NC,1024]
constexpr long long O_CH1   = O_CXLR  + HF((long long)NC * 1024);   // h [NC,512]
constexpr long long O_CXLR2 = O_CH1   + HF((long long)NC * 512);    // h [NC,256]
constexpr long long O_CH2   = O_CXLR2 + HF((long long)NC * 256);    // h [NC,128]
constexpr long long O_WC1T  = O_CH2   + HF((long long)NC * 128);    // h [1024,32]
constexpr long long O_WC2T  = O_WC1T  + HF(1024 * 32);              // h [256,512]
constexpr long long O_WB2T  = O_WC2T  + HF(256 * 512);              // h [256,512]
constexpr long long O_FALO  = O_WB2T  + HF(256 * 512);              // h [1024,64]
constexpr long long O_FAHI  = O_FALO  + HF(1024 * 64);              // h [1024,128]
constexpr long long O_B1LO  = O_FAHI  + HF(1024 * 128);             // h [1024,64]
constexpr long long O_B1HI  = O_B1LO  + HF(1024 * 64);              // h [1024,128]
constexpr long long O_BFH   = O_B1HI  + HF(1024 * 128);             // h [NB,64]
constexpr long long O_BFS   = O_BFH   + HF((long long)NB * 64);     // h [NB,64]
constexpr long long O_WM    = O_BFS   + HF((long long)NB * 64);     // f [NB,2]
constexpr long long O_ZFA   = O_WM    + (long long)NB * 2;          // f [NC,1024]
constexpr long long O_ZB1   = O_ZFA   + (long long)NC * 1024;       // f [NC,1024]
constexpr long long O_BXLR  = O_ZB1   + (long long)NC * 1024;       // h [NB,1024]
constexpr long long O_BH1   = O_BXLR  + HF((long long)NB * 1024);   // h [NB,512]
constexpr long long O_BH2   = O_BH1   + HF((long long)NB * 512);    // h [NB,128]
constexpr long long O_XL3   = O_BH2   + HF((long long)NB * 128);    // f [NB,2]
constexpr long long O_XR3   = O_XL3   + (long long)NB * 2;          // f [NB,2]
constexpr long long O_BCNT  = O_XR3   + (long long)NB * 2;          // i [NB]
constexpr long long O_BEL   = O_BCNT  + (long long)NB;              // i [NB*CAP]
constexpr long long O_CCNT  = O_BEL   + (long long)NB * CAP;        // i [NC]
constexpr long long O_CEL   = O_CCNT  + (long long)NC;              // i [NC*CAP]
constexpr long long SCRATCH_TOTAL = O_CEL + (long long)NC * CAP + 64;

__device__ float g_scratch[SCRATCH_TOTAL];

// ---------------------------------------------------------------------------
__global__ void fillk(float* __restrict__ x, float v, long long n) {
    long long i = (long long)blockIdx.x * blockDim.x + threadIdx.x;
    if (i < n) x[i] = v;
}

__global__ void izero(int* __restrict__ p, int n) {
    int i = blockIdx.x * blockDim.x + threadIdx.x;
    if (i < n) p[i] = 0;
}

__global__ void f2h(const float* __restrict__ src, __half* __restrict__ dst, long long n) {
    long long i = (long long)blockIdx.x * blockDim.x + threadIdx.x;
    if (i < n) dst[i] = __float2half(src[i]);
}

// bfs[n][k] = half(bf[n][k] * wmean[n][0])
__global__ void scale_bf(const float* __restrict__ bf, const float* __restrict__ wm,
                         __half* __restrict__ dst) {
    long long i = (long long)blockIdx.x * blockDim.x + threadIdx.x;
    if (i >= (long long)NB * 64) return;
    int n = (int)(i >> 6);
    dst[i] = __float2half(bf[i] * wm[n * 2]);
}

// Bucket lists store SRC node ids directly.
__global__ void build_lists(const int* __restrict__ ei, int E,
                            int* __restrict__ cnt, int* __restrict__ el)
{
    int e = blockIdx.x * blockDim.x + threadIdx.x;
    if (e >= E) return;
    int s = ei[e];
    int d = ei[E + e];
    int slot = atomicAdd(&cnt[d], 1);
    if (slot < CAP) el[(long long)d * CAP + slot] = s;
}

// out[m][k] (m in [0,2M), k in [0,K)) = fp16 of (m<M ? a[(k0+k)*M+m] : b[(k0+k)*M+m-M])
__global__ void prep_pairT(const float* __restrict__ a, const float* __restrict__ b,
                           __half* __restrict__ out, int K, int M, int k0)
{
    int i = blockIdx.x * blockDim.x + threadIdx.x;
    if (i >= 2 * M * K) return;
    int m = i / K, k = i % K;
    float v = (m < M) ? a[(long long)(k0 + k) * M + m]
                      : b[(long long)(k0 + k) * M + (m - M)];
    out[i] = __float2half(v);
}

// fa_w1 [8,192,128] -> out[m=h*128+j][k] = w[h*192*128 + (k0+k)*128 + j], fp16
__global__ void prep_faT(const float* __restrict__ w, __half* __restrict__ out,
                         int K, int k0)
{
    int i = blockIdx.x * blockDim.x + threadIdx.x;
    if (i >= 1024 * K) return;
    int m = i / K, k = i % K;
    int h = m >> 7, j = m & 127;
    out[i] = __float2half(w[(long long)h * 192 * 128 + (long long)(k0 + k) * 128 + j]);
}

// ---------------------------------------------------------------------------
// FP16 tensor-core GEMM, m16n8k16, 3-stage cp.async pipeline.
// C[N,M] = A[N,K] @ B^T  (B passed TRANSPOSED as [M,K] fp16, k contiguous)
// 128x128x32 CTA tile, 8 warps, warp tile 64x32.
// MODE 0: plain store (+bias, optional relu). CHALF: store fp16 vs fp32.
// MODE 1 (fa): epilogue v = relu(acc + Z[map[row]][col] + bias[col]);
//   head-reduce vs w2; softmax(+b2); atomicAdd 0.125*softmax into wmean.
//   head = blockIdx.x (128 cols per head).
// MODE 2 (b1): store C = acc + ascale[row*2+1] * Z[map[row]][col] (fp16).
// ---------------------------------------------------------------------------
#define AS 40                       // halfs per A smem row (32 + 8 pad)
#define BS 40                       // halfs per B smem row
#define ATILE_B (128 * 80)          // bytes
#define BTILE_B (128 * 80)
#define BUF_B (ATILE_B + BTILE_B)   // 20480 bytes
#define STAGES 3
#define GEMM_SMEM_BYTES (STAGES * BUF_B)   // 61440

__device__ __forceinline__ void cp16(uint32_t d, const void* s, bool pred) {
    int sz = pred ? 16 : 0;
    asm volatile("cp.async.ca.shared.global [%0], [%1], 16, %2;\n"
                 :: "r"(d), "l"(s), "r"(sz));
}

__device__ __forceinline__ void mma16(float* c, unsigned a0, unsigned a1,
                                      unsigned a2, unsigned a3,
                                      unsigned b0, unsigned b1) {
    asm volatile(
        "mma.sync.aligned.m16n8k16.row.col.f32.f16.f16.f32 "
        "{%0,%1,%2,%3},{%4,%5,%6,%7},{%8,%9},{%0,%1,%2,%3};"
        : "+f"(c[0]), "+f"(c[1]), "+f"(c[2]), "+f"(c[3])
        : "r"(a0), "r"(a1), "r"(a2), "r"(a3), "r"(b0), "r"(b1));
}

template<int MODE, bool CHALF>
__global__ void __launch_bounds__(256, 2) hgemm(
    const __half* __restrict__ A, const __half* __restrict__ B,
    void* __restrict__ Cv, const float* __restrict__ bias,
    int N, int K, int M, int relu,
    const float* __restrict__ w2, const float* __restrict__ b2,
    float* __restrict__ wmean,
    const float* __restrict__ zsrc,    // fp32 [NC, M] (MODE 1/2)
    const int*   __restrict__ gmap,    // [N]          (MODE 1/2)
    const float* __restrict__ ascale)  // fp32 [N,2]   (MODE 2)
{
    extern __shared__ char smc[];
    int tid = threadIdx.x;
    int warp = tid >> 5, lane = tid & 31;
    int wm = (warp >> 2) * 64;
    int wn = (warp & 3) * 32;
    int g  = lane >> 2;
    int tg = lane & 3;
    int rowBase = blockIdx.y * 128;
    int colBase = blockIdx.x * 128;

    uint32_t sbase = (uint32_t)__cvta_generic_to_shared(smc);

    float acc[4][4][4] = {};
    int T = K >> 5;

    auto issue_tile = [&](int k0, int buf) {
        uint32_t ab = sbase + (uint32_t)(buf * BUF_B);
        uint32_t bb = ab + ATILE_B;
        #pragma unroll
        for (int it = 0; it < 2; it++) {
            int c = tid + it * 256;
            int r  = c >> 2;
            int kc = (c & 3) << 3;          // 0,8,16,24 halfs
            int gr = rowBase + r;
            bool pa = gr < N;
            cp16(ab + (uint32_t)(r * 80 + kc * 2),
                 A + (long long)(pa ? gr : 0) * K + k0 + kc, pa);
            int n = colBase + r;
            cp16(bb + (uint32_t)(r * 80 + kc * 2),
                 B + (long long)n * K + k0 + kc, true);
        }
        asm volatile("cp.async.commit_group;\n");
    };

    issue_tile(0, 0);
    if (T > 1) issue_tile(32, 1);

    for (int t = 0; t < T; t++) {
        if (t + 1 < T) { asm volatile("cp.async.wait_group 1;\n"); }
        else           { asm volatile("cp.async.wait_group 0;\n"); }
        __syncthreads();
        if (t + 2 < T) issue_tile((t + 2) << 5, (t + 2) % STAGES);

        const __half* as = (const __half*)(smc + (t % STAGES) * BUF_B);
        const __half* bs = as + 128 * AS;

        #pragma unroll
        for (int ks = 0; ks < 32; ks += 16) {
            unsigned aF[4][4], bF[4][2];
            #pragma unroll
            for (int mi = 0; mi < 4; mi++) {
                int m = wm + mi * 16 + g;
                aF[mi][0] = *(const unsigned*)&as[m * AS + ks + 2 * tg];
                aF[mi][1] = *(const unsigned*)&as[(m + 8) * AS + ks + 2 * tg];
                aF[mi][2] = *(const unsigned*)&as[m * AS + ks + 2 * tg + 8];
                aF[mi][3] = *(const unsigned*)&as[(m + 8) * AS + ks + 2 * tg + 8];
            }
            #pragma unroll
            for (int nj = 0; nj < 4; nj++) {
                int n = wn + nj * 8 + g;
                bF[nj][0] = *(const unsigned*)&bs[n * BS + ks + 2 * tg];
                bF[nj][1] = *(const unsigned*)&bs[n * BS + ks + 2 * tg + 8];
            }
            #pragma unroll
            for (int mi = 0; mi < 4; mi++)
                #pragma unroll
                for (int nj = 0; nj < 4; nj++)
                    mma16(acc[mi][nj], aF[mi][0], aF[mi][1], aF[mi][2], aF[mi][3],
                          bF[nj][0], bF[nj][1]);
        }
    }

    if (MODE != 1) {
        #pragma unroll
        for (int mi = 0; mi < 4; mi++) {
            int row = rowBase + wm + mi * 16 + g;
            const float* z0p = nullptr; const float* z1p = nullptr;
            float w1a = 0.f, w1b = 0.f;
            if (MODE == 2) {
                if (row < N)     { z0p = zsrc + (long long)gmap[row] * M;
                                   w1a = ascale[(long long)row * 2 + 1]; }
                if (row + 8 < N) { z1p = zsrc + (long long)gmap[row + 8] * M;
                                   w1b = ascale[(long long)(row + 8) * 2 + 1]; }
            }
            #pragma unroll
            for (int nj = 0; nj < 4; nj++) {
                int col = colBase + wn + nj * 8 + tg * 2;
                float b0 = 0.f, b1 = 0.f;
                if (bias) { b0 = bias[col]; b1 = bias[col + 1]; }
                if (row < N) {
                    float vx = acc[mi][nj][0] + b0, vy = acc[mi][nj][1] + b1;
                    if (MODE == 2) {
                        float2 zv = *(const float2*)(z0p + col);
                        vx += w1a * zv.x; vy += w1a * zv.y;
                    }
                    if (relu) { vx = fmaxf(vx, 0.f); vy = fmaxf(vy, 0.f); }
                    if (CHALF) *(__half2*)((__half*)Cv + (long long)row * M + col) =
                                   __floats2half2_rn(vx, vy);
                    else       *(float2*)((float*)Cv + (long long)row * M + col) =
                                   make_float2(vx, vy);
                }
                if (row + 8 < N) {
                    float vx = acc[mi][nj][2] + b0, vy = acc[mi][nj][3] + b1;
                    if (MODE == 2) {
                        float2 zv = *(const float2*)(z1p + col);
                        vx += w1b * zv.x; vy += w1b * zv.y;
                    }
                    if (relu) { vx = fmaxf(vx, 0.f); vy = fmaxf(vy, 0.f); }
                    if (CHALF) *(__half2*)((__half*)Cv + (long long)(row + 8) * M + col) =
                                   __floats2half2_rn(vx, vy);
                    else       *(float2*)((float*)Cv + (long long)(row + 8) * M + col) =
                                   make_float2(vx, vy);
                }
            }
        }
    } else {
        // fa-head epilogue with Z add. head = blockIdx.x.
        int h = blockIdx.x;
        float* srow = (float*)smc;
        __syncthreads();
        for (int i = tid; i < 256; i += 256) srow[i] = 0.0f;
        __syncthreads();

        #pragma unroll
        for (int mi = 0; mi < 4; mi++) {
            #pragma unroll
            for (int hf = 0; hf < 2; hf++) {
                int rrel = wm + mi * 16 + g + 8 * hf;
                int row = rowBase + rrel;
                if (row >= N) continue;
                const float* zrow = zsrc + (long long)gmap[row] * M + colBase;
                float p0 = 0.f, p1 = 0.f;
                #pragma unroll
                for (int nj = 0; nj < 4; nj++) {
                    int cr = wn + nj * 8 + tg * 2;
                    float a0 = acc[mi][nj][2 * hf];
                    float a1 = acc[mi][nj][2 * hf + 1];
                    float v0 = fmaxf(a0 + zrow[cr] + bias[colBase + cr], 0.f);
                    float v1 = fmaxf(a1 + zrow[cr + 1] + bias[colBase + cr + 1], 0.f);
                    float2 wa = *(const float2*)(w2 + h * 256 + cr * 2);
                    float2 wb = *(const float2*)(w2 + h * 256 + (cr + 1) * 2);
                    p0 += v0 * wa.x + v1 * wb.x;
                    p1 += v0 * wa.y + v1 * wb.y;
                }
                atomicAdd(&srow[rrel * 2 + 0], p0);
                atomicAdd(&srow[rrel * 2 + 1], p1);
            }
        }
        __syncthreads();
        if (tid < 128) {
            int grow = rowBase + tid;
            if (grow < N) {
                float sa = srow[tid * 2 + 0] + b2[h * 2 + 0];
                float sb = srow[tid * 2 + 1] + b2[h * 2 + 1];
                float mx = fmaxf(sa, sb);
                float e0 = expf(sa - mx), e1 = expf(sb - mx);
                float inv = 0.125f / (e0 + e1);
                atomicAdd(&wmean[(long long)grow * 2 + 0], e0 * inv);
                atomicAdd(&wmean[(long long)grow * 2 + 1], e1 * inv);
            }
        }
    }
}

// ---------------------------------------------------------------------------
// Fused GATv2 softmax+aggregate, fp16 in/out, online softmax, 4 halfs/lane.
// One LPG-lane group per (dst, head); D == 4*LPG. ldx in halfs.
// ---------------------------------------------------------------------------
template<int LPG, int D, int H, bool RELU>
__global__ void gat_fused(const int* __restrict__ cnt, const int* __restrict__ el,
                          const __half* __restrict__ xl, const __half* __restrict__ xr,
                          int ldx,
                          const float* __restrict__ att, const float* __restrict__ bias,
                          __half* __restrict__ out, int Nnodes)
{
    static_assert(D == 4 * LPG, "");
    long long t = (long long)blockIdx.x * blockDim.x + threadIdx.x;
    long long gidx = t / LPG;
    int lane = (int)(t % LPG);
    if (gidx >= (long long)Nnodes * H) return;
    int dst = (int)(gidx / H), h = (int)(gidx % H);

    long long roff = (long long)dst * ldx + h * D + lane * 4;
    uint2 ur = *(const uint2*)(xr + roff);
    float2 xr01 = __half22float2(*reinterpret_cast<__half2*>(&ur.x));
    float2 xr23 = __half22float2(*reinterpret_cast<__half2*>(&ur.y));
    float4 a4  = *(const float4*)(att + (long long)h * D + lane * 4);

    int c = cnt[dst]; if (c > CAP) c = CAP;
    const int* lst = el + (long long)dst * CAP;

    float mx = -1e30f, wsum = 0.0f;
    float4 acc = make_float4(0.f, 0.f, 0.f, 0.f);

    for (int i = 0; i <= c; i++) {
        int src = (i == c) ? dst : lst[i];
        uint2 uv = *(const uint2*)(xl + (long long)src * ldx + h * D + lane * 4);
        float2 v01 = __half22float2(*reinterpret_cast<__half2*>(&uv.x));
        float2 v23 = __half22float2(*reinterpret_cast<__half2*>(&uv.y));
        float e0 = v01.x + xr01.x; e0 = e0 > 0.f ? e0 : 0.2f * e0;
        float e1 = v01.y + xr01.y; e1 = e1 > 0.f ? e1 : 0.2f * e1;
        float e2 = v23.x + xr23.x; e2 = e2 > 0.f ? e2 : 0.2f * e2;
        float e3 = v23.y + xr23.y; e3 = e3 > 0.f ? e3 : 0.2f * e3;
        float s = e0 * a4.x + e1 * a4.y + e2 * a4.z + e3 * a4.w;
        #pragma unroll
        for (int o = LPG / 2; o; o >>= 1) s += __shfl_xor_sync(0xffffffffu, s, o, LPG);
        if (s > mx) {
            float f = expf(mx - s);
            wsum *= f;
            acc.x *= f; acc.y *= f; acc.z *= f; acc.w *= f;
            mx = s;
        }
        float p = expf(s - mx);
        wsum += p;
        acc.x += p * v01.x; acc.y += p * v01.y; acc.z += p * v23.x; acc.w += p * v23.y;
    }

    float inv = 1.0f / wsum;
    const float* pb = bias + h * D + lane * 4;
    float o0 = acc.x * inv + pb[0];
    float o1 = acc.y * inv + pb[1];
    float o2 = acc.z * inv + pb[2];
    float o3 = acc.w * inv + pb[3];
    if (RELU) {
        o0 = fmaxf(o0, 0.f); o1 = fmaxf(o1, 0.f);
        o2 = fmaxf(o2, 0.f); o3 = fmaxf(o3, 0.f);
    }
    __half2 h01 = __floats2half2_rn(o0, o1);
    __half2 h23 = __floats2half2_rn(o2, o3);
    uint2 uo;
    uo.x = *reinterpret_cast<unsigned*>(&h01);
    uo.y = *reinterpret_cast<unsigned*>(&h23);
    *(uint2*)(out + ((long long)dst * H + h) * D + lane * 4) = uo;
}

// Layer 3 (H=1, D=2) fused with final log-softmax, writes d_out (fp32).
__global__ void gat3_lsm(const int* __restrict__ cnt, const int* __restrict__ el,
                         const float* __restrict__ xl, const float* __restrict__ xr,
                         const float* __restrict__ att, const float* __restrict__ bias,
                         float* __restrict__ out, int Nnodes)
{
    long long t = (long long)blockIdx.x * blockDim.x + threadIdx.x;
    long long gidx = t >> 1;
    int lane = (int)(t & 1);
    if (gidx >= Nnodes) return;
    int dst = (int)gidx;

    float xr_d = xr[(long long)dst * 2 + lane];
    float a_d  = att[lane];
    int c = cnt[dst]; if (c > CAP) c = CAP;
    const int* lst = el + (long long)dst * CAP;

    float mx = -1e30f, wsum = 0.0f, acc = 0.0f;
    for (int i = 0; i <= c; i++) {
        int src = (i == c) ? dst : lst[i];
        float xv = xl[(long long)src * 2 + lane];
        float v = xv + xr_d;
        v = v > 0.0f ? v : 0.2f * v;
        float s = v * a_d;
        s += __shfl_xor_sync(0xffffffffu, s, 1, 2);
        if (s > mx) {
            float f = expf(mx - s);
            wsum *= f; acc *= f; mx = s;
        }
        float p = expf(s - mx);
        wsum += p;
        acc += p * xv;
    }
    float v = acc / wsum + bias[lane];
    float o = __shfl_xor_sync(0xffffffffu, v, 1, 2);
    float m2 = fmaxf(v, o);
    float lse = m2 + logf(expf(v - m2) + expf(o - m2));
    out[(long long)dst * 2 + lane] = v - lse;
}

// ---------------------------------------------------------------------------
// layer-3 transforms from fp16 features: [N,128] @ [128,2] (wl, wr) -> fp32
__global__ void small_xform(const __half* __restrict__ x, const float* __restrict__ wl,
                            const float* __restrict__ wr, float* __restrict__ xl,
                            float* __restrict__ xr, int N, int K)
{
    int n = blockIdx.x * blockDim.x + threadIdx.x;
    if (n >= N) return;
    float a0 = 0, a1 = 0, b0 = 0, b1 = 0;
    const __half* px = x + (long long)n * K;
    for (int k = 0; k < K; k++) {
        float v = __half2float(px[k]);
        a0 += v * wl[k * 2]; a1 += v * wl[k * 2 + 1];
        b0 += v * wr[k * 2]; b1 += v * wr[k * 2 + 1];
    }
    xl[n * 2] = a0; xl[n * 2 + 1] = a1;
    xr[n * 2] = b0; xr[n * 2 + 1] = b1;
}

// ---------------------------------------------------------------------------
static inline int cdivll(long long a, long long b) { return (int)((a + b - 1) / b); }

extern "C" void kernel_launch(void* const* d_in, const int* in_sizes, int n_in,
                              void* d_out, int out_size)
{
    int idx_bf = 0, idx_cf = 1, idx_bei, idx_cei, idx_map, base_w;
    if (in_sizes[2] == 2 * EB) { idx_bei = 2; idx_cei = 3; idx_map = 4; base_w = 5; }
    else                       { base_w = 2; idx_bei = 26; idx_cei = 27; idx_map = 28; }
    const float* bf  = (const float*)d_in[idx_bf];
    const float* cf  = (const float*)d_in[idx_cf];
    const int*   bei = (const int*)d_in[idx_bei];
    const int*   cei = (const int*)d_in[idx_cei];
    const int*   b2c = (const int*)d_in[idx_map];

    enum { C1WL, C1WR, C1ATT, C1B, C2WL, C2WR, C2ATT, C2B,
           FAW1, FAB1, FAW2, FAB2,
           B1WL, B1WR, B1ATT, B1B, B2WL, B2WR, B2ATT, B2B,
           B3WL, B3WR, B3ATT, B3B };
    const float* W[24];
    for (int i = 0; i < 24; i++) W[i] = (const float*)d_in[base_w + i];

    float* S;
    cudaGetSymbolAddress((void**)&S, g_scratch);
    cudaFuncSetAttribute(hgemm<0, true>,  cudaFuncAttributeMaxDynamicSharedMemorySize, GEMM_SMEM_BYTES);
    cudaFuncSetAttribute(hgemm<0, false>, cudaFuncAttributeMaxDynamicSharedMemorySize, GEMM_SMEM_BYTES);
    cudaFuncSetAttribute(hgemm<1, false>, cudaFuncAttributeMaxDynamicSharedMemorySize, GEMM_SMEM_BYTES);
    cudaFuncSetAttribute(hgemm<2, true>,  cudaFuncAttributeMaxDynamicSharedMemorySize, GEMM_SMEM_BYTES);

    __half* cfh   = (__half*)(S + O_CFH);
    __half* c_xlr = (__half*)(S + O_CXLR);
    __half* c_h1  = (__half*)(S + O_CH1);
    __half* c_xlr2= (__half*)(S + O_CXLR2);
    __half* c_h2  = (__half*)(S + O_CH2);
    __half* Wc1t  = (__half*)(S + O_WC1T);
    __half* Wc2t  = (__half*)(S + O_WC2T);
    __half* Wb2t  = (__half*)(S + O_WB2T);
    __half* faLo  = (__half*)(S + O_FALO);
    __half* faHi  = (__half*)(S + O_FAHI);
    __half* b1Lo  = (__half*)(S + O_B1LO);
    __half* b1Hi  = (__half*)(S + O_B1HI);
    __half* bfh   = (__half*)(S + O_BFH);
    __half* bfs   = (__half*)(S + O_BFS);
    float*  wmean = S + O_WM;
    float*  Zfa   = S + O_ZFA;
    float*  Zb1   = S + O_ZB1;
    __half* b_xlr = (__half*)(S + O_BXLR);
    __half* b_h1  = (__half*)(S + O_BH1);
    __half* b_h2  = (__half*)(S + O_BH2);
    float*  xl3   = S + O_XL3;
    float*  xr3   = S + O_XR3;
    int* bcnt = (int*)(S + O_BCNT);
    int* bel  = (int*)(S + O_BEL);
    int* ccnt = (int*)(S + O_CCNT);
    int* cel  = (int*)(S + O_CEL);

    // ---- Community prep + GNN ----
    f2h<<<cdivll((long long)NC * 32, 256), 256>>>(cf, cfh, (long long)NC * 32);
    prep_pairT<<<cdivll(1024 * 32, 256), 256>>>(W[C1WL], W[C1WR], Wc1t, 32, 512, 0);
    izero<<<cdivll(NC, 256), 256>>>(ccnt, NC);
    build_lists<<<cdivll(EC, 256), 256>>>(cei, EC, ccnt, cel);
    {
        dim3 grid(1024 / 128, (NC + 127) / 128);
        hgemm<0, true><<<grid, 256, GEMM_SMEM_BYTES>>>(
            cfh, Wc1t, c_xlr, nullptr, NC, 32, 1024, 0,
            nullptr, nullptr, nullptr, nullptr, nullptr, nullptr);
    }
    gat_fused<16, 64, 8, true><<<cdivll((long long)NC * 8 * 16, 256), 256>>>(
        ccnt, cel, c_xlr, c_xlr + 512, 1024, W[C1ATT], W[C1B], c_h1, NC);

    prep_pairT<<<cdivll(256 * 512, 256), 256>>>(W[C2WL], W[C2WR], Wc2t, 512, 128, 0);
    {
        dim3 grid(256 / 128, (NC + 127) / 128);
        hgemm<0, true><<<grid, 256, GEMM_SMEM_BYTES>>>(
            c_h1, Wc2t, c_xlr2, nullptr, NC, 512, 256, 0,
            nullptr, nullptr, nullptr, nullptr, nullptr, nullptr);
    }
    gat_fused<8, 32, 4, true><<<cdivll((long long)NC * 4 * 8, 256), 256>>>(
        ccnt, cel, c_xlr2, c_xlr2 + 128, 256, W[C2ATT], W[C2B], c_h2, NC);

    // ---- Building-side prep ----
    prep_faT<<<cdivll(1024 * 64, 256), 256>>>(W[FAW1], faLo, 64, 0);
    prep_faT<<<cdivll(1024 * 128, 256), 256>>>(W[FAW1], faHi, 128, 64);
    prep_pairT<<<cdivll(1024 * 64, 256), 256>>>(W[B1WL], W[B1WR], b1Lo, 64, 512, 0);
    prep_pairT<<<cdivll(1024 * 128, 256), 256>>>(W[B1WL], W[B1WR], b1Hi, 128, 512, 64);
    f2h<<<cdivll((long long)NB * 64, 256), 256>>>(bf, bfh, (long long)NB * 64);
    fillk<<<cdivll((long long)NB * 2, 256), 256>>>(wmean, 0.0f, (long long)NB * 2);
    izero<<<cdivll(NB, 256), 256>>>(bcnt, NB);
    build_lists<<<cdivll(EB, 256), 256>>>(bei, EB, bcnt, bel);

    // ---- Low-rank precompute: Z = c_h2 @ W_hi (fp32 out) ----
    {
        dim3 grid(1024 / 128, (NC + 127) / 128);
        hgemm<0, false><<<grid, 256, GEMM_SMEM_BYTES>>>(
            c_h2, faHi, Zfa, nullptr, NC, 128, 1024, 0,
            nullptr, nullptr, nullptr, nullptr, nullptr, nullptr);
        hgemm<0, false><<<grid, 256, GEMM_SMEM_BYTES>>>(
            c_h2, b1Hi, Zb1, nullptr, NC, 128, 1024, 0,
            nullptr, nullptr, nullptr, nullptr, nullptr, nullptr);
    }

    // ---- Feature attention: acc = bfh @ faLo; epilogue adds Zfa[map] ----
    {
        dim3 grid(1024 / 128, (NB + 127) / 128);
        hgemm<1, false><<<grid, 256, GEMM_SMEM_BYTES>>>(
            bfh, faLo, nullptr, W[FAB1], NB, 64, 1024, 1,
            W[FAW2], W[FAB2], wmean, Zfa, b2c, nullptr);
    }

    // ---- Building GNN ----
    scale_bf<<<cdivll((long long)NB * 64, 256), 256>>>(bf, wmean, bfs);
    {
        dim3 grid(1024 / 128, (NB + 127) / 128);
        hgemm<2, true><<<grid, 256, GEMM_SMEM_BYTES>>>(
            bfs, b1Lo, b_xlr, nullptr, NB, 64, 1024, 0,
            nullptr, nullptr, nullptr, Zb1, b2c, wmean);
    }
    gat_fused<16, 64, 8, true><<<cdivll((long long)NB * 8 * 16, 256), 256>>>(
        bcnt, bel, b_xlr, b_xlr + 512, 1024, W[B1ATT], W[B1B], b_h1, NB);

    prep_pairT<<<cdivll(256 * 512, 256), 256>>>(W[B2WL], W[B2WR], Wb2t, 512, 128, 0);
    {
        dim3 grid(256 / 128, (NB + 127) / 128);
        hgemm<0, true><<<grid, 256, GEMM_SMEM_BYTES>>>(
            b_h1, Wb2t, b_xlr, nullptr, NB, 512, 256, 0,
            nullptr, nullptr, nullptr, nullptr, nullptr, nullptr);
    }
    gat_fused<8, 32, 4, true><<<cdivll((long long)NB * 4 * 8, 256), 256>>>(
        bcnt, bel, b_xlr, b_xlr + 128, 256, W[B2ATT], W[B2B], b_h2, NB);

    small_xform<<<cdivll(NB, 256), 256>>>(b_h2, W[B3WL], W[B3WR], xl3, xr3, NB, 128);
    gat3_lsm<<<cdivll((long long)NB * 2, 256), 256>>>(
        bcnt, bel, xl3, xr3, W[B3ATT], W[B3B], (float*)d_out, NB);
}

// round 13
// speedup vs baseline: 1.4299x; 1.0311x over previous
#include <cuda_runtime.h>
#include <cuda_fp16.h>
#include <math.h>
#include <stdint.h>

// Problem constants
#define NB 100000
#define NC 10000
#define EB 400000
#define EC 80000
#define CAP 64

// halfs -> float slots
#define HF(n) (((n) + 1) / 2)

// ---------------------------------------------------------------------------
// Scratch layout (float units; half/int regions reinterpreted)
// ---------------------------------------------------------------------------
constexpr long long O_CFH   = 0;                                    // h [NC,32]
constexpr long long O_CXLR  = O_CFH   + HF((long long)NC * 32);     // h [NC,1024]
constexpr long long O_CH1   = O_CXLR  + HF((long long)NC * 1024);   // h [NC,512]
constexpr long long O_CXLR2 = O_CH1   + HF((long long)NC * 512);    // h [NC,256]
constexpr long long O_CH2   = O_CXLR2 + HF((long long)NC * 256);    // h [NC,128]
constexpr long long O_WC1T  = O_CH2   + HF((long long)NC * 128);    // h [1024,32]
constexpr long long O_WC2T  = O_WC1T  + HF(1024 * 32);              // h [256,512]
constexpr long long O_WB2T  = O_WC2T  + HF(256 * 512);              // h [256,512]
constexpr long long O_FALO  = O_WB2T  + HF(256 * 512);              // h [1024,64]
constexpr long long O_FAHI  = O_FALO  + HF(1024 * 64);              // h [1024,128]
constexpr long long O_B1LO  = O_FAHI  + HF(1024 * 128);             // h [1024,64]
constexpr long long O_B1HI  = O_B1LO  + HF(1024 * 64);              // h [1024,128]
constexpr long long O_BFH   = O_B1HI  + HF(1024 * 128);             // h [NB,64]
constexpr long long O_BFS   = O_BFH   + HF((long long)NB * 64);     // h [NB,64]
constexpr long long O_WM    = O_BFS   + HF((long long)NB * 64);     // f [NB,2]
constexpr long long O_ZFA   = O_WM    + (long long)NB * 2;          // f [NC,1024]
constexpr long long O_ZB1   = O_ZFA   + (long long)NC * 1024;       // f [NC,1024]
constexpr long long O_BXLR  = O_ZB1   + (long long)NC * 1024;       // h [NB,1024]
constexpr long long O_BH1   = O_BXLR  + HF((long long)NB * 1024);   // h [NB,512]
constexpr long long O_BH2   = O_BH1   + HF((long long)NB * 512);    // h [NB,128]
constexpr long long O_XL3   = O_BH2   + HF((long long)NB * 128);    // f [NB,2]
constexpr long long O_XR3   = O_XL3   + (long long)NB * 2;          // f [NB,2]
constexpr long long O_BCNT  = O_XR3   + (long long)NB * 2;          // i [NB]
constexpr long long O_BEL   = O_BCNT  + (long long)NB;              // i [NB*CAP]
constexpr long long O_CCNT  = O_BEL   + (long long)NB * CAP;        // i [NC]
constexpr long long O_CEL   = O_CCNT  + (long long)NC;              // i [NC*CAP]
constexpr long long SCRATCH_TOTAL = O_CEL + (long long)NC * CAP + 64;

__device__ float g_scratch[SCRATCH_TOTAL];

// ---------------------------------------------------------------------------
// One kernel zeroes bcnt, ccnt, wmean (launched first).
__global__ void zero_misc(int* __restrict__ bcnt, int* __restrict__ ccnt,
                          float* __restrict__ wm)
{
    int i = blockIdx.x * blockDim.x + threadIdx.x;
    if (i < NB) bcnt[i] = 0;
    if (i < NC) ccnt[i] = 0;
    if (i < 2 * NB) wm[i] = 0.0f;
}

__global__ void f2h(const float* __restrict__ src, __half* __restrict__ dst, long long n) {
    long long i = (long long)blockIdx.x * blockDim.x + threadIdx.x;
    if (i < n) dst[i] = __float2half(src[i]);
}

// bfs[n][k] = half(bf[n][k] * wmean[n][0])
__global__ void scale_bf(const float* __restrict__ bf, const float* __restrict__ wm,
                         __half* __restrict__ dst) {
    long long i = (long long)blockIdx.x * blockDim.x + threadIdx.x;
    if (i >= (long long)NB * 64) return;
    int n = (int)(i >> 6);
    dst[i] = __float2half(bf[i] * wm[n * 2]);
}

// Bucket lists store SRC node ids directly.
__global__ void build_lists(const int* __restrict__ ei, int E,
                            int* __restrict__ cnt, int* __restrict__ el)
{
    int e = blockIdx.x * blockDim.x + threadIdx.x;
    if (e >= E) return;
    int s = ei[e];
    int d = ei[E + e];
    int slot = atomicAdd(&cnt[d], 1);
    if (slot < CAP) el[(long long)d * CAP + slot] = s;
}

// out[m][k] (m in [0,2M), k in [0,K)) = fp16 of (m<M ? a[(k0+k)*M+m] : b[(k0+k)*M+m-M])
__global__ void prep_pairT(const float* __restrict__ a, const float* __restrict__ b,
                           __half* __restrict__ out, int K, int M, int k0)
{
    int i = blockIdx.x * blockDim.x + threadIdx.x;
    if (i >= 2 * M * K) return;
    int m = i / K, k = i % K;
    float v = (m < M) ? a[(long long)(k0 + k) * M + m]
                      : b[(long long)(k0 + k) * M + (m - M)];
    out[i] = __float2half(v);
}

// fa_w1 [8,192,128] -> out[m=h*128+j][k] = w[h*192*128 + (k0+k)*128 + j], fp16
__global__ void prep_faT(const float* __restrict__ w, __half* __restrict__ out,
                         int K, int k0)
{
    int i = blockIdx.x * blockDim.x + threadIdx.x;
    if (i >= 1024 * K) return;
    int m = i / K, k = i % K;
    int h = m >> 7, j = m & 127;
    out[i] = __float2half(w[(long long)h * 192 * 128 + (long long)(k0 + k) * 128 + j]);
}

// ---------------------------------------------------------------------------
// FP16 tensor-core GEMM, m16n8k16, 3-stage cp.async pipeline, ldmatrix frags.
// C[N,M] = A[N,K] @ B^T  (B passed TRANSPOSED as [M,K] fp16, k contiguous)
// 128x128x32 CTA tile, 8 warps, warp tile 64x32.
// MODE 0: plain store (+bias, optional relu). CHALF: store fp16 vs fp32.
// MODE 1 (fa): epilogue v = relu(acc + Z[map[row]][col] + bias[col]);
//   head-reduce vs w2; softmax(+b2); atomicAdd 0.125*softmax into wmean.
// MODE 2 (b1): store C = acc + ascale[row*2+1] * Z[map[row]][col] (fp16).
// ---------------------------------------------------------------------------
#define AS 40                       // halfs per A smem row (32 + 8 pad) = 80 B
#define ATILE_B (128 * 80)          // bytes
#define BTILE_B (128 * 80)
#define BUF_B (ATILE_B + BTILE_B)   // 20480 bytes
#define STAGES 3
#define GEMM_SMEM_BYTES (STAGES * BUF_B)   // 61440

__device__ __forceinline__ void cp16(uint32_t d, const void* s, bool pred) {
    int sz = pred ? 16 : 0;
    asm volatile("cp.async.ca.shared.global [%0], [%1], 16, %2;\n"
                 :: "r"(d), "l"(s), "r"(sz));
}

__device__ __forceinline__ void mma16(float* c, unsigned a0, unsigned a1,
                                      unsigned a2, unsigned a3,
                                      unsigned b0, unsigned b1) {
    asm volatile(
        "mma.sync.aligned.m16n8k16.row.col.f32.f16.f16.f32 "
        "{%0,%1,%2,%3},{%4,%5,%6,%7},{%8,%9},{%0,%1,%2,%3};"
        : "+f"(c[0]), "+f"(c[1]), "+f"(c[2]), "+f"(c[3])
        : "r"(a0), "r"(a1), "r"(a2), "r"(a3), "r"(b0), "r"(b1));
}

__device__ __forceinline__ void ldsm4(unsigned& r0, unsigned& r1,
                                      unsigned& r2, unsigned& r3, uint32_t addr) {
    asm volatile("ldmatrix.sync.aligned.m8n8.x4.shared.b16 {%0,%1,%2,%3}, [%4];"
                 : "=r"(r0), "=r"(r1), "=r"(r2), "=r"(r3) : "r"(addr));
}

template<int MODE, bool CHALF>
__global__ void __launch_bounds__(256, 2) hgemm(
    const __half* __restrict__ A, const __half* __restrict__ B,
    void* __restrict__ Cv, const float* __restrict__ bias,
    int N, int K, int M, int relu,
    const float* __restrict__ w2, const float* __restrict__ b2,
    float* __restrict__ wmean,
    const float* __restrict__ zsrc,    // fp32 [NC, M] (MODE 1/2)
    const int*   __restrict__ gmap,    // [N]          (MODE 1/2)
    const float* __restrict__ ascale)  // fp32 [N,2]   (MODE 2)
{
    extern __shared__ char smc[];
    int tid = threadIdx.x;
    int warp = tid >> 5, lane = tid & 31;
    int wm = (warp >> 2) * 64;
    int wn = (warp & 3) * 32;
    int g  = lane >> 2;
    int tg = lane & 3;
    int rowBase = blockIdx.y * 128;
    int colBase = blockIdx.x * 128;

    uint32_t sbase = (uint32_t)__cvta_generic_to_shared(smc);

    // ldmatrix lane-base offsets (bytes, within tile):
    // A x4 matrices: m0: rows wm+lrow, k ks    (lanes 0-7)
    //                m1: rows wm+8+lrow, ks    (lanes 8-15)
    //                m2: rows wm+lrow, ks+8    (lanes 16-23)
    //                m3: rows wm+8+lrow, ks+8  (lanes 24-31)
    int lrow = lane & 7, seg = lane >> 3;
    uint32_t aLane = (uint32_t)((wm + (seg & 1) * 8 + lrow) * 80 + ((seg >> 1) & 1) * 16);
    // B x4 matrices (pair p covers nj=2p, 2p+1):
    //  m0: rows wn+p*16+lrow,   ks    m1: same rows, ks+8
    //  m2: rows wn+p*16+8+lrow, ks    m3: same rows, ks+8
    uint32_t bLane = (uint32_t)((wn + (seg >> 1) * 8 + lrow) * 80 + (seg & 1) * 16);

    float acc[4][4][4] = {};
    int T = K >> 5;

    auto issue_tile = [&](int k0, int buf) {
        uint32_t ab = sbase + (uint32_t)(buf * BUF_B);
        uint32_t bb = ab + ATILE_B;
        #pragma unroll
        for (int it = 0; it < 2; it++) {
            int c = tid + it * 256;
            int r  = c >> 2;
            int kc = (c & 3) << 3;          // 0,8,16,24 halfs
            int gr = rowBase + r;
            bool pa = gr < N;
            cp16(ab + (uint32_t)(r * 80 + kc * 2),
                 A + (long long)(pa ? gr : 0) * K + k0 + kc, pa);
            int n = colBase + r;
            cp16(bb + (uint32_t)(r * 80 + kc * 2),
                 B + (long long)n * K + k0 + kc, true);
        }
        asm volatile("cp.async.commit_group;\n");
    };

    issue_tile(0, 0);
    if (T > 1) issue_tile(32, 1);

    for (int t = 0; t < T; t++) {
        if (t + 1 < T) { asm volatile("cp.async.wait_group 1;\n"); }
        else           { asm volatile("cp.async.wait_group 0;\n"); }
        __syncthreads();
        if (t + 2 < T) issue_tile((t + 2) << 5, (t + 2) % STAGES);

        uint32_t ab = sbase + (uint32_t)((t % STAGES) * BUF_B);
        uint32_t bb = ab + ATILE_B;
        uint32_t aAddr = ab + aLane;
        uint32_t bAddr = bb + bLane;

        #pragma unroll
        for (int ks = 0; ks < 32; ks += 16) {
            unsigned aF[4][4], bF[4][2];
            #pragma unroll
            for (int mi = 0; mi < 4; mi++)
                ldsm4(aF[mi][0], aF[mi][1], aF[mi][2], aF[mi][3],
                      aAddr + (uint32_t)(mi * 16 * 80 + ks * 2));
            #pragma unroll
            for (int p = 0; p < 2; p++)
                ldsm4(bF[2 * p][0], bF[2 * p][1], bF[2 * p + 1][0], bF[2 * p + 1][1],
                      bAddr + (uint32_t)(p * 16 * 80 + ks * 2));
            #pragma unroll
            for (int mi = 0; mi < 4; mi++)
                #pragma unroll
                for (int nj = 0; nj < 4; nj++)
                    mma16(acc[mi][nj], aF[mi][0], aF[mi][1], aF[mi][2], aF[mi][3],
                          bF[nj][0], bF[nj][1]);
        }
    }

    if (MODE != 1) {
        #pragma unroll
        for (int mi = 0; mi < 4; mi++) {
            int row = rowBase + wm + mi * 16 + g;
            const float* z0p = nullptr; const float* z1p = nullptr;
            float w1a = 0.f, w1b = 0.f;
            if (MODE == 2) {
                if (row < N)     { z0p = zsrc + (long long)gmap[row] * M;
                                   w1a = ascale[(long long)row * 2 + 1]; }
                if (row + 8 < N) { z1p = zsrc + (long long)gmap[row + 8] * M;
                                   w1b = ascale[(long long)(row + 8) * 2 + 1]; }
            }
            #pragma unroll
            for (int nj = 0; nj < 4; nj++) {
                int col = colBase + wn + nj * 8 + tg * 2;
                float b0 = 0.f, b1 = 0.f;
                if (bias) { b0 = bias[col]; b1 = bias[col + 1]; }
                if (row < N) {
                    float vx = acc[mi][nj][0] + b0, vy = acc[mi][nj][1] + b1;
                    if (MODE == 2) {
                        float2 zv = *(const float2*)(z0p + col);
                        vx += w1a * zv.x; vy += w1a * zv.y;
                    }
                    if (relu) { vx = fmaxf(vx, 0.f); vy = fmaxf(vy, 0.f); }
                    if (CHALF) *(__half2*)((__half*)Cv + (long long)row * M + col) =
                                   __floats2half2_rn(vx, vy);
                    else       *(float2*)((float*)Cv + (long long)row * M + col) =
                                   make_float2(vx, vy);
                }
                if (row + 8 < N) {
                    float vx = acc[mi][nj][2] + b0, vy = acc[mi][nj][3] + b1;
                    if (MODE == 2) {
                        float2 zv = *(const float2*)(z1p + col);
                        vx += w1b * zv.x; vy += w1b * zv.y;
                    }
                    if (relu) { vx = fmaxf(vx, 0.f); vy = fmaxf(vy, 0.f); }
                    if (CHALF) *(__half2*)((__half*)Cv + (long long)(row + 8) * M + col) =
                                   __floats2half2_rn(vx, vy);
                    else       *(float2*)((float*)Cv + (long long)(row + 8) * M + col) =
                                   make_float2(vx, vy);
                }
            }
        }
    } else {
        // fa-head epilogue with Z add. head = blockIdx.x.
        int h = blockIdx.x;
        float* srow = (float*)smc;
        __syncthreads();
        for (int i = tid; i < 256; i += 256) srow[i] = 0.0f;
        __syncthreads();

        #pragma unroll
        for (int mi = 0; mi < 4; mi++) {
            #pragma unroll
            for (int hf = 0; hf < 2; hf++) {
                int rrel = wm + mi * 16 + g + 8 * hf;
                int row = rowBase + rrel;
                if (row >= N) continue;
                const float* zrow = zsrc + (long long)gmap[row] * M + colBase;
                float p0 = 0.f, p1 = 0.f;
                #pragma unroll
                for (int nj = 0; nj < 4; nj++) {
                    int cr = wn + nj * 8 + tg * 2;
                    float a0 = acc[mi][nj][2 * hf];
                    float a1 = acc[mi][nj][2 * hf + 1];
                    float v0 = fmaxf(a0 + zrow[cr] + bias[colBase + cr], 0.f);
                    float v1 = fmaxf(a1 + zrow[cr + 1] + bias[colBase + cr + 1], 0.f);
                    float2 wa = *(const float2*)(w2 + h * 256 + cr * 2);
                    float2 wb = *(const float2*)(w2 + h * 256 + (cr + 1) * 2);
                    p0 += v0 * wa.x + v1 * wb.x;
                    p1 += v0 * wa.y + v1 * wb.y;
                }
                atomicAdd(&srow[rrel * 2 + 0], p0);
                atomicAdd(&srow[rrel * 2 + 1], p1);
            }
        }
        __syncthreads();
        if (tid < 128) {
            int grow = rowBase + tid;
            if (grow < N) {
                float sa = srow[tid * 2 + 0] + b2[h * 2 + 0];
                float sb = srow[tid * 2 + 1] + b2[h * 2 + 1];
                float mx = fmaxf(sa, sb);
                float e0 = expf(sa - mx), e1 = expf(sb - mx);
                float inv = 0.125f / (e0 + e1);
                atomicAdd(&wmean[(long long)grow * 2 + 0], e0 * inv);
                atomicAdd(&wmean[(long long)grow * 2 + 1], e1 * inv);
            }
        }
    }
}

// ---------------------------------------------------------------------------
// Fused GATv2 softmax+aggregate, fp16 in/out, online softmax, 4 halfs/lane.
// One LPG-lane group per (dst, head); D == 4*LPG. ldx in halfs.
// ---------------------------------------------------------------------------
template<int LPG, int D, int H, bool RELU>
__global__ void gat_fused(const int* __restrict__ cnt, const int* __restrict__ el,
                          const __half* __restrict__ xl, const __half* __restrict__ xr,
                          int ldx,
                          const float* __restrict__ att, const float* __restrict__ bias,
                          __half* __restrict__ out, int Nnodes)
{
    static_assert(D == 4 * LPG, "");
    long long t = (long long)blockIdx.x * blockDim.x + threadIdx.x;
    long long gidx = t / LPG;
    int lane = (int)(t % LPG);
    if (gidx >= (long long)Nnodes * H) return;
    int dst = (int)(gidx / H), h = (int)(gidx % H);

    long long roff = (long long)dst * ldx + h * D + lane * 4;
    uint2 ur = *(const uint2*)(xr + roff);
    float2 xr01 = __half22float2(*reinterpret_cast<__half2*>(&ur.x));
    float2 xr23 = __half22float2(*reinterpret_cast<__half2*>(&ur.y));
    float4 a4  = *(const float4*)(att + (long long)h * D + lane * 4);

    int c = cnt[dst]; if (c > CAP) c = CAP;
    const int* lst = el + (long long)dst * CAP;

    float mx = -1e30f, wsum = 0.0f;
    float4 acc = make_float4(0.f, 0.f, 0.f, 0.f);

    for (int i = 0; i <= c; i++) {
        int src = (i == c) ? dst : lst[i];
        uint2 uv = *(const uint2*)(xl + (long long)src * ldx + h * D + lane * 4);
        float2 v01 = __half22float2(*reinterpret_cast<__half2*>(&uv.x));
        float2 v23 = __half22float2(*reinterpret_cast<__half2*>(&uv.y));
        float e0 = v01.x + xr01.x; e0 = e0 > 0.f ? e0 : 0.2f * e0;
        float e1 = v01.y + xr01.y; e1 = e1 > 0.f ? e1 : 0.2f * e1;
        float e2 = v23.x + xr23.x; e2 = e2 > 0.f ? e2 : 0.2f * e2;
        float e3 = v23.y + xr23.y; e3 = e3 > 0.f ? e3 : 0.2f * e3;
        float s = e0 * a4.x + e1 * a4.y + e2 * a4.z + e3 * a4.w;
        #pragma unroll
        for (int o = LPG / 2; o; o >>= 1) s += __shfl_xor_sync(0xffffffffu, s, o, LPG);
        if (s > mx) {
            float f = expf(mx - s);
            wsum *= f;
            acc.x *= f; acc.y *= f; acc.z *= f; acc.w *= f;
            mx = s;
        }
        float p = expf(s - mx);
        wsum += p;
        acc.x += p * v01.x; acc.y += p * v01.y; acc.z += p * v23.x; acc.w += p * v23.y;
    }

    float inv = 1.0f / wsum;
    const float* pb = bias + h * D + lane * 4;
    float o0 = acc.x * inv + pb[0];
    float o1 = acc.y * inv + pb[1];
    float o2 = acc.z * inv + pb[2];
    float o3 = acc.w * inv + pb[3];
    if (RELU) {
        o0 = fmaxf(o0, 0.f); o1 = fmaxf(o1, 0.f);
        o2 = fmaxf(o2, 0.f); o3 = fmaxf(o3, 0.f);
    }
    __half2 h01 = __floats2half2_rn(o0, o1);
    __half2 h23 = __floats2half2_rn(o2, o3);
    uint2 uo;
    uo.x = *reinterpret_cast<unsigned*>(&h01);
    uo.y = *reinterpret_cast<unsigned*>(&h23);
    *(uint2*)(out + ((long long)dst * H + h) * D + lane * 4) = uo;
}

// Layer 3 (H=1, D=2) fused with final log-softmax, writes d_out (fp32).
__global__ void gat3_lsm(const int* __restrict__ cnt, const int* __restrict__ el,
                         const float* __restrict__ xl, const float* __restrict__ xr,
                         const float* __restrict__ att, const float* __restrict__ bias,
                         float* __restrict__ out, int Nnodes)
{
    long long t = (long long)blockIdx.x * blockDim.x + threadIdx.x;
    long long gidx = t >> 1;
    int lane = (int)(t & 1);
    if (gidx >= Nnodes) return;
    int dst = (int)gidx;

    float xr_d = xr[(long long)dst * 2 + lane];
    float a_d  = att[lane];
    int c = cnt[dst]; if (c > CAP) c = CAP;
    const int* lst = el + (long long)dst * CAP;

    float mx = -1e30f, wsum = 0.0f, acc = 0.0f;
    for (int i = 0; i <= c; i++) {
        int src = (i == c) ? dst : lst[i];
        float xv = xl[(long long)src * 2 + lane];
        float v = xv + xr_d;
        v = v > 0.0f ? v : 0.2f * v;
        float s = v * a_d;
        s += __shfl_xor_sync(0xffffffffu, s, 1, 2);
        if (s > mx) {
            float f = expf(mx - s);
            wsum *= f; acc *= f; mx = s;
        }
        float p = expf(s - mx);
        wsum += p;
        acc += p * xv;
    }
    float v = acc / wsum + bias[lane];
    float o = __shfl_xor_sync(0xffffffffu, v, 1, 2);
    float m2 = fmaxf(v, o);
    float lse = m2 + logf(expf(v - m2) + expf(o - m2));
    out[(long long)dst * 2 + lane] = v - lse;
}

// ---------------------------------------------------------------------------
// layer-3 transforms from fp16 features: [N,128] @ [128,2] (wl, wr) -> fp32
__global__ void small_xform(const __half* __restrict__ x, const float* __restrict__ wl,
                            const float* __restrict__ wr, float* __restrict__ xl,
                            float* __restrict__ xr, int N, int K)
{
    int n = blockIdx.x * blockDim.x + threadIdx.x;
    if (n >= N) return;
    float a0 = 0, a1 = 0, b0 = 0, b1 = 0;
    const __half* px = x + (long long)n * K;
    for (int k = 0; k < K; k++) {
        float v = __half2float(px[k]);
        a0 += v * wl[k * 2]; a1 += v * wl[k * 2 + 1];
        b0 += v * wr[k * 2]; b1 += v * wr[k * 2 + 1];
    }
    xl[n * 2] = a0; xl[n * 2 + 1] = a1;
    xr[n * 2] = b0; xr[n * 2 + 1] = b1;
}

// ---------------------------------------------------------------------------
static inline int cdivll(long long a, long long b) { return (int)((a + b - 1) / b); }

extern "C" void kernel_launch(void* const* d_in, const int* in_sizes, int n_in,
                              void* d_out, int out_size)
{
    int idx_bf = 0, idx_cf = 1, idx_bei, idx_cei, idx_map, base_w;
    if (in_sizes[2] == 2 * EB) { idx_bei = 2; idx_cei = 3; idx_map = 4; base_w = 5; }
    else                       { base_w = 2; idx_bei = 26; idx_cei = 27; idx_map = 28; }
    const float* bf  = (const float*)d_in[idx_bf];
    const float* cf  = (const float*)d_in[idx_cf];
    const int*   bei = (const int*)d_in[idx_bei];
    const int*   cei = (const int*)d_in[idx_cei];
    const int*   b2c = (const int*)d_in[idx_map];

    enum { C1WL, C1WR, C1ATT, C1B, C2WL, C2WR, C2ATT, C2B,
           FAW1, FAB1, FAW2, FAB2,
           B1WL, B1WR, B1ATT, B1B, B2WL, B2WR, B2ATT, B2B,
           B3WL, B3WR, B3ATT, B3B };
    const float* W[24];
    for (int i = 0; i < 24; i++) W[i] = (const float*)d_in[base_w + i];

    float* S;
    cudaGetSymbolAddress((void**)&S, g_scratch);
    cudaFuncSetAttribute(hgemm<0, true>,  cudaFuncAttributeMaxDynamicSharedMemorySize, GEMM_SMEM_BYTES);
    cudaFuncSetAttribute(hgemm<0, false>, cudaFuncAttributeMaxDynamicSharedMemorySize, GEMM_SMEM_BYTES);
    cudaFuncSetAttribute(hgemm<1, false>, cudaFuncAttributeMaxDynamicSharedMemorySize, GEMM_SMEM_BYTES);
    cudaFuncSetAttribute(hgemm<2, true>,  cudaFuncAttributeMaxDynamicSharedMemorySize, GEMM_SMEM_BYTES);

    __half* cfh   = (__half*)(S + O_CFH);
    __half* c_xlr = (__half*)(S + O_CXLR);
    __half* c_h1  = (__half*)(S + O_CH1);
    __half* c_xlr2= (__half*)(S + O_CXLR2);
    __half* c_h2  = (__half*)(S + O_CH2);
    __half* Wc1t  = (__half*)(S + O_WC1T);
    __half* Wc2t  = (__half*)(S + O_WC2T);
    __half* Wb2t  = (__half*)(S + O_WB2T);
    __half* faLo  = (__half*)(S + O_FALO);
    __half* faHi  = (__half*)(S + O_FAHI);
    __half* b1Lo  = (__half*)(S + O_B1LO);
    __half* b1Hi  = (__half*)(S + O_B1HI);
    __half* bfh   = (__half*)(S + O_BFH);
    __half* bfs   = (__half*)(S + O_BFS);
    float*  wmean = S + O_WM;
    float*  Zfa   = S + O_ZFA;
    float*  Zb1   = S + O_ZB1;
    __half* b_xlr = (__half*)(S + O_BXLR);
    __half* b_h1  = (__half*)(S + O_BH1);
    __half* b_h2  = (__half*)(S + O_BH2);
    float*  xl3   = S + O_XL3;
    float*  xr3   = S + O_XR3;
    int* bcnt = (int*)(S + O_BCNT);
    int* bel  = (int*)(S + O_BEL);
    int* ccnt = (int*)(S + O_CCNT);
    int* cel  = (int*)(S + O_CEL);

    // ---- Zeroing + graph prep ----
    zero_misc<<<cdivll(2 * NB, 256), 256>>>(bcnt, ccnt, wmean);
    build_lists<<<cdivll(EC, 256), 256>>>(cei, EC, ccnt, cel);
    build_lists<<<cdivll(EB, 256), 256>>>(bei, EB, bcnt, bel);

    // ---- Community prep + GNN ----
    f2h<<<cdivll((long long)NC * 32, 256), 256>>>(cf, cfh, (long long)NC * 32);
    prep_pairT<<<cdivll(1024 * 32, 256), 256>>>(W[C1WL], W[C1WR], Wc1t, 32, 512, 0);
    {
        dim3 grid(1024 / 128, (NC + 127) / 128);
        hgemm<0, true><<<grid, 256, GEMM_SMEM_BYTES>>>(
            cfh, Wc1t, c_xlr, nullptr, NC, 32, 1024, 0,
            nullptr, nullptr, nullptr, nullptr, nullptr, nullptr);
    }
    gat_fused<16, 64, 8, true><<<cdivll((long long)NC * 8 * 16, 256), 256>>>(
        ccnt, cel, c_xlr, c_xlr + 512, 1024, W[C1ATT], W[C1B], c_h1, NC);

    prep_pairT<<<cdivll(256 * 512, 256), 256>>>(W[C2WL], W[C2WR], Wc2t, 512, 128, 0);
    {
        dim3 grid(256 / 128, (NC + 127) / 128);
        hgemm<0, true><<<grid, 256, GEMM_SMEM_BYTES>>>(
            c_h1, Wc2t, c_xlr2, nullptr, NC, 512, 256, 0,
            nullptr, nullptr, nullptr, nullptr, nullptr, nullptr);
    }
    gat_fused<8, 32, 4, true><<<cdivll((long long)NC * 4 * 8, 256), 256>>>(
        ccnt, cel, c_xlr2, c_xlr2 + 128, 256, W[C2ATT], W[C2B], c_h2, NC);

    // ---- Building-side prep ----
    prep_faT<<<cdivll(1024 * 64, 256), 256>>>(W[FAW1], faLo, 64, 0);
    prep_faT<<<cdivll(1024 * 128, 256), 256>>>(W[FAW1], faHi, 128, 64);
    prep_pairT<<<cdivll(1024 * 64, 256), 256>>>(W[B1WL], W[B1WR], b1Lo, 64, 512, 0);
    prep_pairT<<<cdivll(1024 * 128, 256), 256>>>(W[B1WL], W[B1WR], b1Hi, 128, 512, 64);
    f2h<<<cdivll((long long)NB * 64, 256), 256>>>(bf, bfh, (long long)NB * 64);

    // ---- Low-rank precompute: Z = c_h2 @ W_hi (fp32 out) ----
    {
        dim3 grid(1024 / 128, (NC + 127) / 128);
        hgemm<0, false><<<grid, 256, GEMM_SMEM_BYTES>>>(
            c_h2, faHi, Zfa, nullptr, NC, 128, 1024, 0,
            nullptr, nullptr, nullptr, nullptr, nullptr, nullptr);
        hgemm<0, false><<<grid, 256, GEMM_SMEM_BYTES>>>(
            c_h2, b1Hi, Zb1, nullptr, NC, 128, 1024, 0,
            nullptr, nullptr, nullptr, nullptr, nullptr, nullptr);
    }

    // ---- Feature attention: acc = bfh @ faLo; epilogue adds Zfa[map] ----
    {
        dim3 grid(1024 / 128, (NB + 127) / 128);
        hgemm<1, false><<<grid, 256, GEMM_SMEM_BYTES>>>(
            bfh, faLo, nullptr, W[FAB1], NB, 64, 1024, 1,
            W[FAW2], W[FAB2], wmean, Zfa, b2c, nullptr);
    }

    // ---- Building GNN ----
    scale_bf<<<cdivll((long long)NB * 64, 256), 256>>>(bf, wmean, bfs);
    {
        dim3 grid(1024 / 128, (NB + 127) / 128);
        hgemm<2, true><<<grid, 256, GEMM_SMEM_BYTES>>>(
            bfs, b1Lo, b_xlr, nullptr, NB, 64, 1024, 0,
            nullptr, nullptr, nullptr, Zb1, b2c, wmean);
    }
    gat_fused<16, 64, 8, true><<<cdivll((long long)NB * 8 * 16, 256), 256>>>(
        bcnt, bel, b_xlr, b_xlr + 512, 1024, W[B1ATT], W[B1B], b_h1, NB);

    prep_pairT<<<cdivll(256 * 512, 256), 256>>>(W[B2WL], W[B2WR], Wb2t, 512, 128, 0);
    {
        dim3 grid(256 / 128, (NB + 127) / 128);
        hgemm<0, true><<<grid, 256, GEMM_SMEM_BYTES>>>(
            b_h1, Wb2t, b_xlr, nullptr, NB, 512, 256, 0,
            nullptr, nullptr, nullptr, nullptr, nullptr, nullptr);
    }
    gat_fused<8, 32, 4, true><<<cdivll((long long)NB * 4 * 8, 256), 256>>>(
        bcnt, bel, b_xlr, b_xlr + 128, 256, W[B2ATT], W[B2B], b_h2, NB);

    small_xform<<<cdivll(NB, 256), 256>>>(b_h2, W[B3WL], W[B3WR], xl3, xr3, NB, 128);
    gat3_lsm<<<cdivll((long long)NB * 2, 256), 256>>>(
        bcnt, bel, xl3, xr3, W[B3ATT], W[B3B], (float*)d_out, NB);
}